// round 3
// baseline (speedup 1.0000x reference)
#include <cuda_runtime.h>
#include <cstdint>
#include <cstddef>
#include <climits>

// ---------------------------------------------------------------------------
// Problem shape (fixed by the dataset)
//   inputs:   [16, 2048, 1024] f32  -> M = 32768 tokens, D = 1024
//   codebook: [2048, 1024]     f32  -> K = 2048 codes
// Outputs concatenated (f32):
//   quantized  [32768,1024]  @ 0
//   qloss      [32768,2048]  @ 33554432   (scalar broadcast)
//   nn_idx     [32768]       @ 100663296  (as float)
//   codebook   [2048,1024]   @ 100696064
// ---------------------------------------------------------------------------
#define M_TOK   32768
#define K_CODE  2048
#define D_DIM   1024

#define QUANT_OFF 0
#define LOSS_OFF  33554432
#define NN_OFF    100663296
#define CB_OFF    100696064
#define LOSS_N    67108864
#define CB_N      2097152

#define NCAND 8

// ------------------------- scratch (device globals) ------------------------
__device__ float g_logits[(size_t)M_TOK * K_CODE];   // 256 MiB
#define RP_CTAS 256
__device__ float g_div_part[RP_CTAS * K_CODE];       // per-CTA diversity partials
__device__ float g_h_part[RP_CTAS];                  // per-CTA sum of p*log2(p) partials
__device__ int   g_nn[M_TOK];
__device__ float g_loss[1];
__device__ int   g_cand_cnt[M_TOK];
__device__ int   g_cand_idx[M_TOK][NCAND];

// ---------------------------------------------------------------------------
// Kernel 1: fp32 SGEMM (NT):  S[m,n] = dot(A[m,:], B[n,:])
// 128x128 tile, BK=8, 256 threads, 8x8 per thread, double-buffered smem.
// ---------------------------------------------------------------------------
#define BM 128
#define BN 128
#define BK 8

__global__ __launch_bounds__(256, 2)
void sgemm_nt_kernel(const float* __restrict__ A,   // [M_TOK, D_DIM]
                     const float* __restrict__ B,   // [K_CODE, D_DIM]
                     float* __restrict__ C)         // [M_TOK, K_CODE]
{
    __shared__ float As[2][BK][BM];
    __shared__ float Bs[2][BK][BN];

    const int tid = threadIdx.x;
    const int bm = blockIdx.y * BM;
    const int bn = blockIdx.x * BN;

    // loaders: one float4 per thread per tile (128 rows x 8 k)
    const int lrow = tid >> 1;          // 0..127
    const int lcol = (tid & 1) * 4;     // 0 or 4
    const float* Aptr = A + (size_t)(bm + lrow) * D_DIM + lcol;
    const float* Bptr = B + (size_t)(bn + lrow) * D_DIM + lcol;

    // compute mapping: 16x16 threads, 8x8 per thread
    const int tx = tid & 15;
    const int ty = tid >> 4;

    float acc[8][8];
#pragma unroll
    for (int i = 0; i < 8; ++i)
#pragma unroll
        for (int j = 0; j < 8; ++j) acc[i][j] = 0.f;

    const int NT = D_DIM / BK;   // 128

    float4 aReg = *(const float4*)(Aptr);
    float4 bReg = *(const float4*)(Bptr);
    As[0][lcol + 0][lrow] = aReg.x;  As[0][lcol + 1][lrow] = aReg.y;
    As[0][lcol + 2][lrow] = aReg.z;  As[0][lcol + 3][lrow] = aReg.w;
    Bs[0][lcol + 0][lrow] = bReg.x;  Bs[0][lcol + 1][lrow] = bReg.y;
    Bs[0][lcol + 2][lrow] = bReg.z;  Bs[0][lcol + 3][lrow] = bReg.w;
    __syncthreads();

    int buf = 0;
    for (int kt = 0; kt < NT; ++kt) {
        const bool has_next = (kt + 1 < NT);
        if (has_next) {
            aReg = *(const float4*)(Aptr + (kt + 1) * BK);
            bReg = *(const float4*)(Bptr + (kt + 1) * BK);
        }
#pragma unroll
        for (int kk = 0; kk < BK; ++kk) {
            float af[8], bf[8];
            *(float4*)(af)     = *(const float4*)&As[buf][kk][ty * 8];
            *(float4*)(af + 4) = *(const float4*)&As[buf][kk][ty * 8 + 4];
            *(float4*)(bf)     = *(const float4*)&Bs[buf][kk][tx * 8];
            *(float4*)(bf + 4) = *(const float4*)&Bs[buf][kk][tx * 8 + 4];
#pragma unroll
            for (int i = 0; i < 8; ++i)
#pragma unroll
                for (int j = 0; j < 8; ++j)
                    acc[i][j] = fmaf(af[i], bf[j], acc[i][j]);
        }
        if (has_next) {
            buf ^= 1;
            As[buf][lcol + 0][lrow] = aReg.x;  As[buf][lcol + 1][lrow] = aReg.y;
            As[buf][lcol + 2][lrow] = aReg.z;  As[buf][lcol + 3][lrow] = aReg.w;
            Bs[buf][lcol + 0][lrow] = bReg.x;  Bs[buf][lcol + 1][lrow] = bReg.y;
            Bs[buf][lcol + 2][lrow] = bReg.z;  Bs[buf][lcol + 3][lrow] = bReg.w;
            __syncthreads();
        }
    }

#pragma unroll
    for (int i = 0; i < 8; ++i) {
        float* crow = C + (size_t)(bm + ty * 8 + i) * K_CODE + bn + tx * 8;
        float4 v0 = make_float4(acc[i][0], acc[i][1], acc[i][2], acc[i][3]);
        float4 v1 = make_float4(acc[i][4], acc[i][5], acc[i][6], acc[i][7]);
        *(float4*)(crow)     = v0;
        *(float4*)(crow + 4) = v1;
    }
}

// ---------------------------------------------------------------------------
// fast 2^y (degree-6 poly after round-to-nearest split); avoids MUFU cliff.
// ---------------------------------------------------------------------------
__device__ __forceinline__ float fast_exp2(float y)
{
    float r = rintf(y);
    float f = y - r;                       // [-0.5, 0.5]
    float p = 1.5403530e-4f;
    p = fmaf(p, f, 1.3333558e-3f);
    p = fmaf(p, f, 9.6181291e-3f);
    p = fmaf(p, f, 5.5504109e-2f);
    p = fmaf(p, f, 2.4022651e-1f);
    p = fmaf(p, f, 6.9314718e-1f);
    p = fmaf(p, f, 1.0f);
    int ei = (int)r;
    if (ei < -126) return 0.f;
    float s = __int_as_float((ei + 127) << 23);
    return p * s;
}

// ---------------------------------------------------------------------------
// Kernel 2: per-token row pass over logits.
//   - max + argmax-candidate collection (all codes within 0.01 of max)
//   - s0 = sum exp(l-m), s1 = sum exp(l-m)*(l-m)*log2e
//   - token entropy term: sum_k p*log2(p+eps) ~= s1/s0 - log2(s0)
//   - diversity partials accumulated per-thread in registers (no atomics)
// 256 CTAs x 256 threads, 128 tokens per CTA.
// ---------------------------------------------------------------------------
#define TOK_PER_CTA (M_TOK / RP_CTAS)   // 128

__global__ __launch_bounds__(256)
void row_pass_kernel(const float* __restrict__ S)
{
    const int tid = threadIdx.x;
    const int cta = blockIdx.x;
    const int lane = tid & 31;
    const int warp = tid >> 5;

    __shared__ float wm[8];
    __shared__ float ws0[8], ws1[8];
    __shared__ float bc_m, bc_s0, bc_s1;
    __shared__ int   s_cnt;
    __shared__ int   s_cidx[NCAND];

    float dreg[8];
#pragma unroll
    for (int j = 0; j < 8; ++j) dreg[j] = 0.f;
    float hsum = 0.f;

    for (int t = 0; t < TOK_PER_CTA; ++t) {
        const int tok = cta * TOK_PER_CTA + t;
        const float* row = S + (size_t)tok * K_CODE;

        float lv[8];
#pragma unroll
        for (int j = 0; j < 8; ++j) lv[j] = row[tid + j * 256];

        // ---- max ----
        float m = lv[0];
#pragma unroll
        for (int j = 1; j < 8; ++j) m = fmaxf(m, lv[j]);
#pragma unroll
        for (int off = 16; off > 0; off >>= 1)
            m = fmaxf(m, __shfl_xor_sync(0xffffffffu, m, off));
        if (lane == 0) wm[warp] = m;
        __syncthreads();
        if (tid == 0) {
            float bmv = wm[0];
#pragma unroll
            for (int w = 1; w < 8; ++w) bmv = fmaxf(bmv, wm[w]);
            bc_m = bmv;
            s_cnt = 0;
        }
        __syncthreads();
        m = bc_m;

        // ---- candidate collection (anything within 0.01 of max; fp32 GEMM
        // abs error << 0.01 so the true argmax is always in this set) ----
        const float thr = m - 0.01f;
#pragma unroll
        for (int j = 0; j < 8; ++j) {
            if (lv[j] >= thr) {
                int p = atomicAdd(&s_cnt, 1);
                if (p < NCAND) s_cidx[p] = tid + j * 256;
            }
        }

        // ---- exp / sums ----
        const float LOG2E = 1.4426950408889634f;
        float s0 = 0.f, s1 = 0.f, ev[8];
#pragma unroll
        for (int j = 0; j < 8; ++j) {
            float y = (lv[j] - m) * LOG2E;     // log2 of unnormalized p
            float e = fast_exp2(y);
            ev[j] = e;
            s0 += e;
            s1 = fmaf(e, y, s1);
        }
#pragma unroll
        for (int off = 16; off > 0; off >>= 1) {
            s0 += __shfl_down_sync(0xffffffffu, s0, off);
            s1 += __shfl_down_sync(0xffffffffu, s1, off);
        }
        if (lane == 0) { ws0[warp] = s0; ws1[warp] = s1; }
        __syncthreads();
        if (tid == 0) {
            float t0 = 0.f, t1 = 0.f;
#pragma unroll
            for (int w = 0; w < 8; ++w) { t0 += ws0[w]; t1 += ws1[w]; }
            bc_s0 = t0; bc_s1 = t1;
        }
        __syncthreads();
        const float S0 = bc_s0;
        const float inv = 1.f / S0;

#pragma unroll
        for (int j = 0; j < 8; ++j) dreg[j] = fmaf(ev[j], inv, dreg[j]);

        // export candidates
        const int cnt = (s_cnt < NCAND) ? s_cnt : NCAND;
        if (tid < cnt) g_cand_idx[tok][tid] = s_cidx[tid];
        if (tid == 0) {
            g_cand_cnt[tok] = cnt;
            // sum_k p*log2 p  =  s1/s0 - log2(s0)
            hsum += bc_s1 * inv - log2f(S0);
        }
        __syncthreads();   // protect shared slots for next token
    }

#pragma unroll
    for (int j = 0; j < 8; ++j)
        g_div_part[(size_t)cta * K_CODE + tid + j * 256] = dreg[j];
    if (tid == 0) g_h_part[cta] = hsum;
}

// ---------------------------------------------------------------------------
// Kernel 2b: fp64 refinement of argmax for near-tied tokens.
// One warp per token. For cnt==1 this is just the fp32 argmax; for cnt>1
// (expected ~tens of tokens total) recompute exact dots in fp64 and pick the
// winner (lowest index on exact tie, matching jnp.argmax semantics).
// ---------------------------------------------------------------------------
__global__ __launch_bounds__(256)
void refine_kernel(const float* __restrict__ inputs,
                   const float* __restrict__ codebook,
                   float* __restrict__ nn_out)
{
    const int warp = threadIdx.x >> 5;
    const int lane = threadIdx.x & 31;
    const int tok = blockIdx.x * 8 + warp;

    const int cnt = g_cand_cnt[tok];
    int best = g_cand_idx[tok][0];

    if (cnt > 1) {
        const float* xr = inputs + (size_t)tok * D_DIM;
        double bv = -1e300;
        int bi = INT_MAX;
        for (int c = 0; c < cnt; ++c) {
            const int idx = g_cand_idx[tok][c];
            const float* cr = codebook + (size_t)idx * D_DIM;
            double s = 0.0;
            for (int i = lane; i < D_DIM; i += 32)
                s += (double)xr[i] * (double)cr[i];
#pragma unroll
            for (int off = 16; off > 0; off >>= 1)
                s += __shfl_down_sync(0xffffffffu, s, off);
            s = __shfl_sync(0xffffffffu, s, 0);
            if (s > bv || (s == bv && idx < bi)) { bv = s; bi = idx; }
        }
        best = bi;
    }

    if (lane == 0) {
        g_nn[tok] = best;
        nn_out[tok] = (float)best;
    }
}

// ---------------------------------------------------------------------------
// Kernel 3: finalize loss (single CTA, deterministic tree reductions)
// ---------------------------------------------------------------------------
__global__ __launch_bounds__(256)
void finalize_kernel()
{
    const int tid = threadIdx.x;
    float d[8];
#pragma unroll
    for (int j = 0; j < 8; ++j) d[j] = 0.f;
    for (int c = 0; c < RP_CTAS; ++c) {
#pragma unroll
        for (int j = 0; j < 8; ++j)
            d[j] += g_div_part[(size_t)c * K_CODE + tid + j * 256];
    }
    float acc = 0.f;
#pragma unroll
    for (int j = 0; j < 8; ++j) {
        float dv = d[j] * (1.f / (float)M_TOK);
        acc += dv * log2f(dv + 1e-8f);
    }
    float h = g_h_part[tid];   // 256 partials, one per thread

    __shared__ float sa[256], sh[256];
    sa[tid] = acc; sh[tid] = h;
    __syncthreads();
    for (int off = 128; off > 0; off >>= 1) {
        if (tid < off) { sa[tid] += sa[tid + off]; sh[tid] += sh[tid + off]; }
        __syncthreads();
    }
    if (tid == 0) {
        float h_clust = -sh[0] / (float)M_TOK;
        // loss = h_clust - h_div ; h_div = -sa[0]  =>  loss = h_clust + sa[0]
        g_loss[0] = h_clust + sa[0];
    }
}

// ---------------------------------------------------------------------------
// Kernel 4: fill the quantization_loss region with the scalar loss
// ---------------------------------------------------------------------------
__global__ __launch_bounds__(256)
void fill_loss_kernel(float* __restrict__ dst)
{
    const float v = g_loss[0];
    const float4 v4 = make_float4(v, v, v, v);
    size_t i = ((size_t)blockIdx.x * blockDim.x + threadIdx.x);
    const size_t stride = (size_t)gridDim.x * blockDim.x;
    const size_t n4 = LOSS_N / 4;
    float4* d4 = (float4*)dst;
    for (; i < n4; i += stride) d4[i] = v4;
}

// ---------------------------------------------------------------------------
// Kernel 5: copy codebook into output
// ---------------------------------------------------------------------------
__global__ __launch_bounds__(256)
void copy_cb_kernel(const float* __restrict__ src, float* __restrict__ dst)
{
    size_t i = ((size_t)blockIdx.x * blockDim.x + threadIdx.x);
    const size_t stride = (size_t)gridDim.x * blockDim.x;
    const size_t n4 = CB_N / 4;
    const float4* s4 = (const float4*)src;
    float4* d4 = (float4*)dst;
    for (; i < n4; i += stride) d4[i] = s4[i];
}

// ---------------------------------------------------------------------------
// Kernel 6: gather codebook rows, center + L2-normalize, then apply the
// straight-through identity out = inputs + (q - inputs) elementwise (matches
// reference rounding). One warp per token.
// ---------------------------------------------------------------------------
__global__ __launch_bounds__(256)
void quantize_kernel(const float* __restrict__ inputs,
                     const float* __restrict__ codebook,
                     float* __restrict__ qout)
{
    const int warp = threadIdx.x >> 5;
    const int lane = threadIdx.x & 31;
    const int tok = blockIdx.x * 8 + warp;
    const int idx = g_nn[tok];
    const float* row = codebook + (size_t)idx * D_DIM;

    float4 x[8];
    float sum = 0.f;
#pragma unroll
    for (int c = 0; c < 8; ++c) {
        x[c] = *(const float4*)(row + c * 128 + lane * 4);
        sum += x[c].x + x[c].y + x[c].z + x[c].w;
    }
#pragma unroll
    for (int off = 16; off > 0; off >>= 1)
        sum += __shfl_xor_sync(0xffffffffu, sum, off);
    const float mean = sum * (1.f / (float)D_DIM);

    float ss = 0.f;
#pragma unroll
    for (int c = 0; c < 8; ++c) {
        x[c].x -= mean; x[c].y -= mean; x[c].z -= mean; x[c].w -= mean;
        ss += x[c].x * x[c].x + x[c].y * x[c].y + x[c].z * x[c].z + x[c].w * x[c].w;
    }
#pragma unroll
    for (int off = 16; off > 0; off >>= 1)
        ss += __shfl_xor_sync(0xffffffffu, ss, off);
    const float inv = rsqrtf(ss) * sqrtf(ss) / ss;   // = 1/sqrt(ss) refined
    const float invn = 1.f / sqrtf(ss);

    const float* xin = inputs + (size_t)tok * D_DIM;
    float* out = qout + (size_t)tok * D_DIM;
    (void)inv;
#pragma unroll
    for (int c = 0; c < 8; ++c) {
        float4 iv = *(const float4*)(xin + c * 128 + lane * 4);
        float4 v;
        v.x = iv.x + (x[c].x * invn - iv.x);
        v.y = iv.y + (x[c].y * invn - iv.y);
        v.z = iv.z + (x[c].z * invn - iv.z);
        v.w = iv.w + (x[c].w * invn - iv.w);
        *(float4*)(out + c * 128 + lane * 4) = v;
    }
}

// ---------------------------------------------------------------------------
extern "C" void kernel_launch(void* const* d_in, const int* in_sizes, int n_in,
                              void* d_out, int out_size)
{
    const float* inputs   = (const float*)d_in[0];
    const float* codebook = (const float*)d_in[1];
    float* out = (float*)d_out;

    float* logits;
    cudaGetSymbolAddress((void**)&logits, g_logits);

    // 1) similarity GEMM
    {
        dim3 grid(K_CODE / BN, M_TOK / BM);   // (16, 256)
        sgemm_nt_kernel<<<grid, 256>>>(inputs, codebook, logits);
    }
    // 2) row pass: max / candidates / softmax stats / diversity partials
    row_pass_kernel<<<RP_CTAS, 256>>>(logits);
    // 2b) fp64 refine of near-tied argmax -> final nn_idx
    refine_kernel<<<M_TOK / 8, 256>>>(inputs, codebook, out + NN_OFF);
    // 3) finalize scalar loss
    finalize_kernel<<<1, 256>>>();
    // 4) broadcast loss
    fill_loss_kernel<<<8192, 256>>>(out + LOSS_OFF);
    // 5) codebook passthrough
    copy_cb_kernel<<<2048, 256>>>(codebook, out + CB_OFF);
    // 6) quantized rows (straight-through identity applied like the reference)
    quantize_kernel<<<M_TOK / 8, 256>>>(inputs, codebook, out + QUANT_OFF);
}

// round 10
// speedup vs baseline: 2.3350x; 2.3350x over previous
#include <cuda_runtime.h>
#include <cuda_bf16.h>
#include <cstdint>
#include <cstddef>
#include <climits>

// ---------------------------------------------------------------------------
// Problem shape (fixed by the dataset)
//   inputs:   [16, 2048, 1024] f32  -> M = 32768 tokens, D = 1024
//   codebook: [2048, 1024]     f32  -> K = 2048 codes
// Outputs concatenated (f32):
//   quantized  [32768,1024]  @ 0
//   qloss      [32768,2048]  @ 33554432   (scalar broadcast)
//   nn_idx     [32768]       @ 100663296  (as float)
//   codebook   [2048,1024]   @ 100696064
// ---------------------------------------------------------------------------
#define M_TOK   32768
#define K_CODE  2048
#define D_DIM   1024

#define QUANT_OFF 0
#define LOSS_OFF  33554432
#define NN_OFF    100663296
#define CB_OFF    100696064
#define LOSS_N    67108864
#define CB_N      2097152

#define NCAND 8

// ------------------------- scratch (device globals) ------------------------
__device__ float g_logits[(size_t)M_TOK * K_CODE];   // 256 MiB
#define RP_CTAS 256
__device__ float g_div_part[RP_CTAS * K_CODE];
__device__ float g_h_part[RP_CTAS];
__device__ float g_acc_part[16];
__device__ int   g_nn[M_TOK];
__device__ float g_loss[1];
__device__ int   g_cand_cnt[M_TOK];
__device__ int   g_cand_idx[M_TOK][NCAND];

// bf16 split operands, pre-tiled + pre-SW128-swizzled into 16KB blocks of
// [128 rows x 64 cols bf16] (= 128 rows x 128B).
//   A blocks ordered [m_tile (256)][k_chunk (16)]
//   B blocks ordered [k_chunk (16)][n_block (16)]
__device__ uint4 g_Ahi[(size_t)M_TOK * D_DIM / 8];   // 64 MiB
__device__ uint4 g_Alo[(size_t)M_TOK * D_DIM / 8];   // 64 MiB
__device__ uint4 g_Bhi[(size_t)K_CODE * D_DIM / 8];  // 4 MiB
__device__ uint4 g_Blo[(size_t)K_CODE * D_DIM / 8];  // 4 MiB

// ------------------------- PTX helpers ---------------------------
__device__ __forceinline__ uint32_t smem_to_u32(const void* p) {
    uint32_t a;
    asm("{ .reg .u64 t; cvta.to.shared.u64 t, %1; cvt.u32.u64 %0, t; }" : "=r"(a) : "l"(p));
    return a;
}

__device__ __forceinline__ void cp_async16(uint32_t dst, const void* src) {
    asm volatile("cp.async.cg.shared.global [%0], [%1], 16;" :: "r"(dst), "l"(src) : "memory");
}
__device__ __forceinline__ void cp_commit() {
    asm volatile("cp.async.commit_group;" ::: "memory");
}
template <int N>
__device__ __forceinline__ void cp_wait() {
    asm volatile("cp.async.wait_group %0;" :: "n"(N) : "memory");
}

__device__ __forceinline__ void ldmatrix_x4(uint32_t& r0, uint32_t& r1,
                                            uint32_t& r2, uint32_t& r3, uint32_t addr) {
    asm volatile("ldmatrix.sync.aligned.m8n8.x4.shared.b16 {%0,%1,%2,%3}, [%4];"
                 : "=r"(r0), "=r"(r1), "=r"(r2), "=r"(r3) : "r"(addr));
}

__device__ __forceinline__ void mma_bf16(float* c, const uint32_t* a, const uint32_t* b) {
    asm volatile(
        "mma.sync.aligned.m16n8k16.row.col.f32.bf16.bf16.f32 "
        "{%0,%1,%2,%3}, {%4,%5,%6,%7}, {%8,%9}, {%0,%1,%2,%3};"
        : "+f"(c[0]), "+f"(c[1]), "+f"(c[2]), "+f"(c[3])
        : "r"(a[0]), "r"(a[1]), "r"(a[2]), "r"(a[3]), "r"(b[0]), "r"(b[1]));
}

// ---------------------------------------------------------------------------
// Kernel 0: fp32 -> (bf16 hi, bf16 lo), tiled into 16KB SW128-swizzled blocks.
// One thread = 8 consecutive columns (16B of bf16 output per array).
// blk = tile*tileStride + kc*kcStride   (A: 16,1   B: 1,16)
// ---------------------------------------------------------------------------
__global__ __launch_bounds__(256)
void split_kernel(const float* __restrict__ src,
                  uint4* __restrict__ hi, uint4* __restrict__ lo,
                  int nchunks, int tileStride, int kcStride)
{
    int i = blockIdx.x * blockDim.x + threadIdx.x;
    if (i >= nchunks) return;
    const int c8   = i & 127;      // column group (8 cols of 1024)
    const int row  = i >> 7;
    const int kc   = c8 >> 3;      // k-chunk 0..15
    const int g    = c8 & 7;       // 16B group within 128B row
    const int tile = row >> 7;
    const int r    = row & 127;

    const size_t blk = (size_t)tile * tileStride + (size_t)kc * kcStride;
    uint32_t off = r * 128 + g * 16;
    off ^= (off >> 3) & 0x70;                     // SW128 swizzle
    const size_t dst = blk * 1024 + (off >> 4);   // uint4 units (16KB block = 1024 uint4)

    const float4* s4 = (const float4*)(src + ((size_t)row << 10) + (c8 << 3));
    float4 x0 = s4[0], x1 = s4[1];
    float xs[8] = {x0.x, x0.y, x0.z, x0.w, x1.x, x1.y, x1.z, x1.w};
    uint32_t hw[4], lw[4];
#pragma unroll
    for (int j = 0; j < 4; ++j) {
        float a = xs[2*j], b = xs[2*j+1];
        __nv_bfloat16 h0 = __float2bfloat16_rn(a);
        __nv_bfloat16 h1 = __float2bfloat16_rn(b);
        __nv_bfloat16 l0 = __float2bfloat16_rn(a - __bfloat162float(h0));
        __nv_bfloat16 l1 = __float2bfloat16_rn(b - __bfloat162float(h1));
        hw[j] = (uint32_t)__bfloat16_as_ushort(h0) | ((uint32_t)__bfloat16_as_ushort(h1) << 16);
        lw[j] = (uint32_t)__bfloat16_as_ushort(l0) | ((uint32_t)__bfloat16_as_ushort(l1) << 16);
    }
    hi[dst] = make_uint4(hw[0], hw[1], hw[2], hw[3]);
    lo[dst] = make_uint4(lw[0], lw[1], lw[2], lw[3]);
}

// ---------------------------------------------------------------------------
// Kernel 1: bf16 3-split GEMM via warp-level mma.sync (HMMA path; works on
// vanilla compute_103 PTX where tcgen05 is rejected).
// CTA tile 128(M) x 128(N), BK=64 bf16 per stage; 48 stages = 3 passes x 16
// k-chunks (hi*hi, hi*lo, lo*hi) accumulated in fp32 registers.
// 8 warps, warp tile 64x32 (4 m-tiles x 4 n-tiles of m16n8k16).
// 3-stage cp.async pipeline; stage buffers are the pre-swizzled 16KB blocks,
// so stage loads are plain linear 16B copies.
// ---------------------------------------------------------------------------
#define G_STAGE_BYTES 32768
#define G_SMEM_TOTAL  (3 * G_STAGE_BYTES)   // 98304

__device__ __forceinline__ void gemm_copy_stage(
    uint32_t sbuf, int it, int mt, int nt, int tid,
    const uint8_t* Ahi, const uint8_t* Alo,
    const uint8_t* Bhi, const uint8_t* Blo)
{
    const int p = it >> 4, kc = it & 15;
    const uint8_t* Asrc = (p < 2 ? Ahi : Alo) + ((size_t)(mt * 16 + kc)) * 16384;
    const uint8_t* Bsrc = (p == 1 ? Blo : Bhi) + ((size_t)(kc * 16 + nt)) * 16384;
#pragma unroll
    for (int i = 0; i < 4; ++i) {
        const int ch = tid + i * 256;
        cp_async16(sbuf + ch * 16,          Asrc + (size_t)ch * 16);
        cp_async16(sbuf + 16384 + ch * 16,  Bsrc + (size_t)ch * 16);
    }
    cp_commit();
}

__global__ __launch_bounds__(256, 2)
void gemm_bf16x3_mma_kernel(const uint8_t* __restrict__ Ahi, const uint8_t* __restrict__ Alo,
                            const uint8_t* __restrict__ Bhi, const uint8_t* __restrict__ Blo,
                            float* __restrict__ C)
{
    extern __shared__ char smem[];
    const uint32_t sb = smem_to_u32(smem);
    const int tid = threadIdx.x;
    const int wid = tid >> 5;
    const int lane = tid & 31;
    const int nt = blockIdx.x;   // 0..15  (N tile of 128)
    const int mt = blockIdx.y;   // 0..255 (M tile of 128)

    const int wm = (wid >> 2) * 64;   // warp m offset in tile
    const int wn = (wid & 3) * 32;    // warp n offset in tile

    float acc[4][4][4];
#pragma unroll
    for (int i = 0; i < 4; ++i)
#pragma unroll
        for (int j = 0; j < 4; ++j)
#pragma unroll
            for (int r = 0; r < 4; ++r) acc[i][j][r] = 0.f;

    // prefetch 3 stages
    gemm_copy_stage(sb + 0 * G_STAGE_BYTES, 0, mt, nt, tid, Ahi, Alo, Bhi, Blo);
    gemm_copy_stage(sb + 1 * G_STAGE_BYTES, 1, mt, nt, tid, Ahi, Alo, Bhi, Blo);
    gemm_copy_stage(sb + 2 * G_STAGE_BYTES, 2, mt, nt, tid, Ahi, Alo, Bhi, Blo);

    // precomputed ldmatrix lane addressing pieces
    const int lrow15 = lane & 15;     // row within 16-row tile
    const int lhalf  = lane >> 4;     // 0: k 0-7, 1: k 8-15 (16B unit select)

    for (int it = 0; it < 48; ++it) {
        if (it < 46)       cp_wait<2>();
        else if (it == 46) cp_wait<1>();
        else               cp_wait<0>();
        __syncthreads();

        const uint32_t aBase = sb + (uint32_t)(it % 3) * G_STAGE_BYTES;
        const uint32_t bBase = aBase + 16384;

#pragma unroll
        for (int kk = 0; kk < 4; ++kk) {
            const int unit = 2 * kk + lhalf;
            uint32_t a[4][4];
            uint32_t b[4][2];
#pragma unroll
            for (int mi = 0; mi < 4; ++mi) {
                const int row = wm + mi * 16 + lrow15;
                const uint32_t addr = aBase + row * 128 + ((unit ^ (row & 7)) << 4);
                ldmatrix_x4(a[mi][0], a[mi][1], a[mi][2], a[mi][3], addr);
            }
#pragma unroll
            for (int j = 0; j < 2; ++j) {
                const int row = wn + j * 16 + lrow15;
                const uint32_t addr = bBase + row * 128 + ((unit ^ (row & 7)) << 4);
                uint32_t r0, r1, r2, r3;
                ldmatrix_x4(r0, r1, r2, r3, addr);
                b[2*j][0] = r0;  b[2*j][1] = r2;      // n-tile 2j:   k0-7, k8-15
                b[2*j+1][0] = r1; b[2*j+1][1] = r3;   // n-tile 2j+1
            }
#pragma unroll
            for (int mi = 0; mi < 4; ++mi)
#pragma unroll
                for (int ni = 0; ni < 4; ++ni)
                    mma_bf16(acc[mi][ni], a[mi], b[ni]);
        }

        __syncthreads();
        if (it + 3 < 48)
            gemm_copy_stage(sb + (uint32_t)((it + 3) % 3) * G_STAGE_BYTES,
                            it + 3, mt, nt, tid, Ahi, Alo, Bhi, Blo);
    }

    // epilogue: d-frag -> C
    const int rbase = mt * 128 + wm + (lane >> 2);
    const int cbase = nt * 128 + wn + 2 * (lane & 3);
#pragma unroll
    for (int mi = 0; mi < 4; ++mi) {
#pragma unroll
        for (int ni = 0; ni < 4; ++ni) {
            const int r0 = rbase + mi * 16;
            const int c0 = cbase + ni * 8;
            float2* p0 = (float2*)(C + (size_t)r0 * K_CODE + c0);
            float2* p1 = (float2*)(C + (size_t)(r0 + 8) * K_CODE + c0);
            *p0 = make_float2(acc[mi][ni][0], acc[mi][ni][1]);
            *p1 = make_float2(acc[mi][ni][2], acc[mi][ni][3]);
        }
    }
}

// ---------------------------------------------------------------------------
// fast 2^y (degree-6 poly after round-to-nearest split); avoids MUFU cliff.
// ---------------------------------------------------------------------------
__device__ __forceinline__ float fast_exp2(float y)
{
    float r = rintf(y);
    float f = y - r;
    float p = 1.5403530e-4f;
    p = fmaf(p, f, 1.3333558e-3f);
    p = fmaf(p, f, 9.6181291e-3f);
    p = fmaf(p, f, 5.5504109e-2f);
    p = fmaf(p, f, 2.4022651e-1f);
    p = fmaf(p, f, 6.9314718e-1f);
    p = fmaf(p, f, 1.0f);
    int ei = (int)r;
    if (ei < -126) return 0.f;
    float s = __int_as_float((ei + 127) << 23);
    return p * s;
}

// ---------------------------------------------------------------------------
// Kernel 2: per-token row pass (max/candidates, softmax stats, diversity).
// ---------------------------------------------------------------------------
#define TOK_PER_CTA (M_TOK / RP_CTAS)   // 128

__global__ __launch_bounds__(256)
void row_pass_kernel(const float* __restrict__ S)
{
    const int tid = threadIdx.x;
    const int cta = blockIdx.x;
    const int lane = tid & 31;
    const int warp = tid >> 5;

    __shared__ float wm[8];
    __shared__ float ws0[8], ws1[8];
    __shared__ float bc_m, bc_s0, bc_s1;
    __shared__ int   s_cnt;
    __shared__ int   s_cidx[NCAND];

    float dreg[8];
#pragma unroll
    for (int j = 0; j < 8; ++j) dreg[j] = 0.f;
    float hsum = 0.f;

    for (int t = 0; t < TOK_PER_CTA; ++t) {
        const int tok = cta * TOK_PER_CTA + t;
        const float* row = S + (size_t)tok * K_CODE;

        float lv[8];
#pragma unroll
        for (int j = 0; j < 8; ++j) lv[j] = row[tid + j * 256];

        float m = lv[0];
#pragma unroll
        for (int j = 1; j < 8; ++j) m = fmaxf(m, lv[j]);
#pragma unroll
        for (int off = 16; off > 0; off >>= 1)
            m = fmaxf(m, __shfl_xor_sync(0xffffffffu, m, off));
        if (lane == 0) wm[warp] = m;
        __syncthreads();
        if (tid == 0) {
            float bmv = wm[0];
#pragma unroll
            for (int w = 1; w < 8; ++w) bmv = fmaxf(bmv, wm[w]);
            bc_m = bmv;
            s_cnt = 0;
        }
        __syncthreads();
        m = bc_m;

        const float thr = m - 0.01f;
#pragma unroll
        for (int j = 0; j < 8; ++j) {
            if (lv[j] >= thr) {
                int p = atomicAdd(&s_cnt, 1);
                if (p < NCAND) s_cidx[p] = tid + j * 256;
            }
        }

        const float LOG2E = 1.4426950408889634f;
        float s0 = 0.f, s1 = 0.f, ev[8];
#pragma unroll
        for (int j = 0; j < 8; ++j) {
            float y = (lv[j] - m) * LOG2E;
            float e = fast_exp2(y);
            ev[j] = e;
            s0 += e;
            s1 = fmaf(e, y, s1);
        }
#pragma unroll
        for (int off = 16; off > 0; off >>= 1) {
            s0 += __shfl_down_sync(0xffffffffu, s0, off);
            s1 += __shfl_down_sync(0xffffffffu, s1, off);
        }
        if (lane == 0) { ws0[warp] = s0; ws1[warp] = s1; }
        __syncthreads();
        if (tid == 0) {
            float t0 = 0.f, t1 = 0.f;
#pragma unroll
            for (int w = 0; w < 8; ++w) { t0 += ws0[w]; t1 += ws1[w]; }
            bc_s0 = t0; bc_s1 = t1;
        }
        __syncthreads();
        const float S0 = bc_s0;
        const float inv = 1.f / S0;

#pragma unroll
        for (int j = 0; j < 8; ++j) dreg[j] = fmaf(ev[j], inv, dreg[j]);

        const int cnt = (s_cnt < NCAND) ? s_cnt : NCAND;
        if (tid < cnt) g_cand_idx[tok][tid] = s_cidx[tid];
        if (tid == 0) {
            g_cand_cnt[tok] = cnt;
            hsum += bc_s1 * inv - log2f(S0);
        }
        __syncthreads();
    }

#pragma unroll
    for (int j = 0; j < 8; ++j)
        g_div_part[(size_t)cta * K_CODE + tid + j * 256] = dreg[j];
    if (tid == 0) g_h_part[cta] = hsum;
}

// ---------------------------------------------------------------------------
// Kernel 2b: fp64 refinement of argmax for near-tied tokens (1 warp/token).
// ---------------------------------------------------------------------------
__global__ __launch_bounds__(256)
void refine_kernel(const float* __restrict__ inputs,
                   const float* __restrict__ codebook,
                   float* __restrict__ nn_out)
{
    const int warp = threadIdx.x >> 5;
    const int lane = threadIdx.x & 31;
    const int tok = blockIdx.x * 8 + warp;

    const int cnt = g_cand_cnt[tok];
    int best = g_cand_idx[tok][0];

    if (cnt > 1) {
        const float* xr = inputs + (size_t)tok * D_DIM;
        double bv = -1e300;
        int bi = INT_MAX;
        for (int c = 0; c < cnt; ++c) {
            const int idx = g_cand_idx[tok][c];
            const float* cr = codebook + (size_t)idx * D_DIM;
            double s = 0.0;
            for (int i = lane; i < D_DIM; i += 32)
                s += (double)xr[i] * (double)cr[i];
#pragma unroll
            for (int off = 16; off > 0; off >>= 1)
                s += __shfl_down_sync(0xffffffffu, s, off);
            s = __shfl_sync(0xffffffffu, s, 0);
            if (s > bv || (s == bv && idx < bi)) { bv = s; bi = idx; }
        }
        best = bi;
    }

    if (lane == 0) {
        g_nn[tok] = best;
        nn_out[tok] = (float)best;
    }
}

// ---------------------------------------------------------------------------
// Kernel 3a: diversity reduce across the 256 per-CTA partials (16 CTAs).
// ---------------------------------------------------------------------------
__global__ __launch_bounds__(128)
void div_reduce_kernel()
{
    const int col = blockIdx.x * 128 + threadIdx.x;
    float s = 0.f;
#pragma unroll 8
    for (int c = 0; c < RP_CTAS; ++c)
        s += g_div_part[(size_t)c * K_CODE + col];
    float dv = s * (1.f / (float)M_TOK);
    float acc = dv * log2f(dv + 1e-8f);

    __shared__ float sa[128];
    sa[threadIdx.x] = acc;
    __syncthreads();
    for (int off = 64; off > 0; off >>= 1) {
        if (threadIdx.x < off) sa[threadIdx.x] += sa[threadIdx.x + off];
        __syncthreads();
    }
    if (threadIdx.x == 0) g_acc_part[blockIdx.x] = sa[0];
}

// ---------------------------------------------------------------------------
// Kernel 3b: final scalar loss.
// ---------------------------------------------------------------------------
__global__ __launch_bounds__(256)
void finalize2_kernel()
{
    const int tid = threadIdx.x;
    float h = g_h_part[tid];
    float a = (tid < 16) ? g_acc_part[tid] : 0.f;

    __shared__ float sh[256], sa[256];
    sh[tid] = h; sa[tid] = a;
    __syncthreads();
    for (int off = 128; off > 0; off >>= 1) {
        if (tid < off) { sh[tid] += sh[tid + off]; sa[tid] += sa[tid + off]; }
        __syncthreads();
    }
    if (tid == 0) {
        float h_clust = -sh[0] / (float)M_TOK;
        g_loss[0] = h_clust + sa[0];   // loss = h_clust - (-sa) = h_clust + sa
    }
}

// ---------------------------------------------------------------------------
// Kernel 4: broadcast scalar loss into the qloss region.
// ---------------------------------------------------------------------------
__global__ __launch_bounds__(256)
void fill_loss_kernel(float* __restrict__ dst)
{
    const float v = g_loss[0];
    const float4 v4 = make_float4(v, v, v, v);
    size_t i = ((size_t)blockIdx.x * blockDim.x + threadIdx.x);
    const size_t stride = (size_t)gridDim.x * blockDim.x;
    const size_t n4 = LOSS_N / 4;
    float4* d4 = (float4*)dst;
    for (; i < n4; i += stride) d4[i] = v4;
}

// ---------------------------------------------------------------------------
// Kernel 5: copy codebook into output.
// ---------------------------------------------------------------------------
__global__ __launch_bounds__(256)
void copy_cb_kernel(const float* __restrict__ src, float* __restrict__ dst)
{
    size_t i = ((size_t)blockIdx.x * blockDim.x + threadIdx.x);
    const size_t stride = (size_t)gridDim.x * blockDim.x;
    const size_t n4 = CB_N / 4;
    const float4* s4 = (const float4*)src;
    float4* d4 = (float4*)dst;
    for (; i < n4; i += stride) d4[i] = s4[i];
}

// ---------------------------------------------------------------------------
// Kernel 6: gather + center + L2-normalize + straight-through identity.
// ---------------------------------------------------------------------------
__global__ __launch_bounds__(256)
void quantize_kernel(const float* __restrict__ inputs,
                     const float* __restrict__ codebook,
                     float* __restrict__ qout)
{
    const int warp = threadIdx.x >> 5;
    const int lane = threadIdx.x & 31;
    const int tok = blockIdx.x * 8 + warp;
    const int idx = g_nn[tok];
    const float* row = codebook + (size_t)idx * D_DIM;

    float4 x[8];
    float sum = 0.f;
#pragma unroll
    for (int c = 0; c < 8; ++c) {
        x[c] = *(const float4*)(row + c * 128 + lane * 4);
        sum += x[c].x + x[c].y + x[c].z + x[c].w;
    }
#pragma unroll
    for (int off = 16; off > 0; off >>= 1)
        sum += __shfl_xor_sync(0xffffffffu, sum, off);
    const float mean = sum * (1.f / (float)D_DIM);

    float ss = 0.f;
#pragma unroll
    for (int c = 0; c < 8; ++c) {
        x[c].x -= mean; x[c].y -= mean; x[c].z -= mean; x[c].w -= mean;
        ss += x[c].x * x[c].x + x[c].y * x[c].y + x[c].z * x[c].z + x[c].w * x[c].w;
    }
#pragma unroll
    for (int off = 16; off > 0; off >>= 1)
        ss += __shfl_xor_sync(0xffffffffu, ss, off);
    const float invn = 1.f / sqrtf(ss);

    const float* xin = inputs + (size_t)tok * D_DIM;
    float* out = qout + (size_t)tok * D_DIM;
#pragma unroll
    for (int c = 0; c < 8; ++c) {
        float4 iv = *(const float4*)(xin + c * 128 + lane * 4);
        float4 v;
        v.x = iv.x + (x[c].x * invn - iv.x);
        v.y = iv.y + (x[c].y * invn - iv.y);
        v.z = iv.z + (x[c].z * invn - iv.z);
        v.w = iv.w + (x[c].w * invn - iv.w);
        *(float4*)(out + c * 128 + lane * 4) = v;
    }
}

// ---------------------------------------------------------------------------
extern "C" void kernel_launch(void* const* d_in, const int* in_sizes, int n_in,
                              void* d_out, int out_size)
{
    const float* inputs   = (const float*)d_in[0];
    const float* codebook = (const float*)d_in[1];
    float* out = (float*)d_out;

    float *logits;
    uint4 *Ahi, *Alo, *Bhi, *Blo;
    cudaGetSymbolAddress((void**)&logits, g_logits);
    cudaGetSymbolAddress((void**)&Ahi, g_Ahi);
    cudaGetSymbolAddress((void**)&Alo, g_Alo);
    cudaGetSymbolAddress((void**)&Bhi, g_Bhi);
    cudaGetSymbolAddress((void**)&Blo, g_Blo);

    // 0) split fp32 -> bf16 hi/lo, pre-tiled + swizzled
    split_kernel<<<(M_TOK * 128) / 256, 256>>>(inputs, Ahi, Alo, M_TOK * 128, 16, 1);
    split_kernel<<<(K_CODE * 128) / 256, 256>>>(codebook, Bhi, Blo, K_CODE * 128, 1, 16);

    // 1) bf16 3-split similarity GEMM (warp mma.sync path)
    cudaFuncSetAttribute(gemm_bf16x3_mma_kernel,
                         cudaFuncAttributeMaxDynamicSharedMemorySize, G_SMEM_TOTAL);
    {
        dim3 grid(K_CODE / 128, M_TOK / 128);   // (16, 256)
        gemm_bf16x3_mma_kernel<<<grid, 256, G_SMEM_TOTAL>>>(
            (const uint8_t*)Ahi, (const uint8_t*)Alo,
            (const uint8_t*)Bhi, (const uint8_t*)Blo, logits);
    }

    // 2) row pass
    row_pass_kernel<<<RP_CTAS, 256>>>(logits);
    // 2b) fp64 refine of near-tied argmax -> final nn_idx
    refine_kernel<<<M_TOK / 8, 256>>>(inputs, codebook, out + NN_OFF);
    // 3) loss reduction
    div_reduce_kernel<<<16, 128>>>();
    finalize2_kernel<<<1, 256>>>();
    // 4) broadcast loss
    fill_loss_kernel<<<8192, 256>>>(out + LOSS_OFF);
    // 5) codebook passthrough
    copy_cb_kernel<<<2048, 256>>>(codebook, out + CB_OFF);
    // 6) quantized rows
    quantize_kernel<<<M_TOK / 8, 256>>>(inputs, codebook, out + QUANT_OFF);
}

// round 11
// speedup vs baseline: 2.3384x; 1.0015x over previous
#include <cuda_runtime.h>
#include <cuda_bf16.h>
#include <cstdint>
#include <cstddef>
#include <climits>

// ---------------------------------------------------------------------------
// Problem shape (fixed by the dataset)
//   inputs:   [16, 2048, 1024] f32  -> M = 32768 tokens, D = 1024
//   codebook: [2048, 1024]     f32  -> K = 2048 codes
// Outputs concatenated (f32):
//   quantized  [32768,1024]  @ 0
//   qloss      [32768,2048]  @ 33554432   (scalar broadcast)
//   nn_idx     [32768]       @ 100663296  (as float)
//   codebook   [2048,1024]   @ 100696064
// ---------------------------------------------------------------------------
#define M_TOK   32768
#define K_CODE  2048
#define D_DIM   1024

#define QUANT_OFF 0
#define LOSS_OFF  33554432
#define NN_OFF    100663296
#define CB_OFF    100696064
#define LOSS_N    67108864
#define CB_N      2097152

#define NCAND 8

// ------------------------- scratch (device globals) ------------------------
__device__ float g_logits[(size_t)M_TOK * K_CODE];   // 256 MiB
#define RP_CTAS 256
__device__ float g_div_part[RP_CTAS * K_CODE];
__device__ float g_h_part[RP_CTAS];
__device__ float g_acc_part[16];
__device__ int   g_nn[M_TOK];
__device__ float g_loss[1];
__device__ int   g_cand_cnt[M_TOK];
__device__ int   g_cand_idx[M_TOK][NCAND];

// bf16 split operands, pre-tiled + pre-SW128-swizzled into 16KB blocks of
// [128 rows x 64 cols bf16] (= 128 rows x 128B).
//   A blocks ordered [m_tile (256)][k_chunk (16)]
//   B blocks ordered [k_chunk (16)][n_block (16)]
__device__ uint4 g_Ahi[(size_t)M_TOK * D_DIM / 8];   // 64 MiB
__device__ uint4 g_Alo[(size_t)M_TOK * D_DIM / 8];   // 64 MiB
__device__ uint4 g_Bhi[(size_t)K_CODE * D_DIM / 8];  // 4 MiB
__device__ uint4 g_Blo[(size_t)K_CODE * D_DIM / 8];  // 4 MiB

// ------------------------- PTX helpers ---------------------------
__device__ __forceinline__ uint32_t smem_to_u32(const void* p) {
    uint32_t a;
    asm("{ .reg .u64 t; cvta.to.shared.u64 t, %1; cvt.u32.u64 %0, t; }" : "=r"(a) : "l"(p));
    return a;
}

__device__ __forceinline__ void cp_async16(uint32_t dst, const void* src) {
    asm volatile("cp.async.cg.shared.global [%0], [%1], 16;" :: "r"(dst), "l"(src) : "memory");
}
__device__ __forceinline__ void cp_commit() {
    asm volatile("cp.async.commit_group;" ::: "memory");
}
template <int N>
__device__ __forceinline__ void cp_wait() {
    asm volatile("cp.async.wait_group %0;" :: "n"(N) : "memory");
}

__device__ __forceinline__ void ldmatrix_x4(uint32_t& r0, uint32_t& r1,
                                            uint32_t& r2, uint32_t& r3, uint32_t addr) {
    asm volatile("ldmatrix.sync.aligned.m8n8.x4.shared.b16 {%0,%1,%2,%3}, [%4];"
                 : "=r"(r0), "=r"(r1), "=r"(r2), "=r"(r3) : "r"(addr));
}

__device__ __forceinline__ void mma_bf16(float* c, const uint32_t* a, const uint32_t* b) {
    asm volatile(
        "mma.sync.aligned.m16n8k16.row.col.f32.bf16.bf16.f32 "
        "{%0,%1,%2,%3}, {%4,%5,%6,%7}, {%8,%9}, {%0,%1,%2,%3};"
        : "+f"(c[0]), "+f"(c[1]), "+f"(c[2]), "+f"(c[3])
        : "r"(a[0]), "r"(a[1]), "r"(a[2]), "r"(a[3]), "r"(b[0]), "r"(b[1]));
}

// ---------------------------------------------------------------------------
// Kernel 0: fp32 -> (bf16 hi, bf16 lo), tiled into 16KB SW128-swizzled blocks.
// One thread = 8 consecutive columns (16B of bf16 output per array).
// blk = tile*tileStride + kc*kcStride   (A: 16,1   B: 1,16)
// ---------------------------------------------------------------------------
__global__ __launch_bounds__(256)
void split_kernel(const float* __restrict__ src,
                  uint4* __restrict__ hi, uint4* __restrict__ lo,
                  int nchunks, int tileStride, int kcStride)
{
    int i = blockIdx.x * blockDim.x + threadIdx.x;
    if (i >= nchunks) return;
    const int c8   = i & 127;      // column group (8 cols of 1024)
    const int row  = i >> 7;
    const int kc   = c8 >> 3;      // k-chunk 0..15
    const int g    = c8 & 7;       // 16B group within 128B row
    const int tile = row >> 7;
    const int r    = row & 127;

    const size_t blk = (size_t)tile * tileStride + (size_t)kc * kcStride;
    uint32_t off = r * 128 + g * 16;
    off ^= (off >> 3) & 0x70;                     // SW128 swizzle
    const size_t dst = blk * 1024 + (off >> 4);   // uint4 units (16KB block = 1024 uint4)

    const float4* s4 = (const float4*)(src + ((size_t)row << 10) + (c8 << 3));
    float4 x0 = s4[0], x1 = s4[1];
    float xs[8] = {x0.x, x0.y, x0.z, x0.w, x1.x, x1.y, x1.z, x1.w};
    uint32_t hw[4], lw[4];
#pragma unroll
    for (int j = 0; j < 4; ++j) {
        float a = xs[2*j], b = xs[2*j+1];
        __nv_bfloat16 h0 = __float2bfloat16_rn(a);
        __nv_bfloat16 h1 = __float2bfloat16_rn(b);
        __nv_bfloat16 l0 = __float2bfloat16_rn(a - __bfloat162float(h0));
        __nv_bfloat16 l1 = __float2bfloat16_rn(b - __bfloat162float(h1));
        hw[j] = (uint32_t)__bfloat16_as_ushort(h0) | ((uint32_t)__bfloat16_as_ushort(h1) << 16);
        lw[j] = (uint32_t)__bfloat16_as_ushort(l0) | ((uint32_t)__bfloat16_as_ushort(l1) << 16);
    }
    hi[dst] = make_uint4(hw[0], hw[1], hw[2], hw[3]);
    lo[dst] = make_uint4(lw[0], lw[1], lw[2], lw[3]);
}

// ---------------------------------------------------------------------------
// Kernel 1: bf16 3-split GEMM via warp-level mma.sync (HMMA path; works on
// vanilla compute_103 PTX where tcgen05 is rejected).
// CTA tile 128(M) x 128(N), BK=64 bf16 per stage; 48 stages = 3 passes x 16
// k-chunks (hi*hi, hi*lo, lo*hi) accumulated in fp32 registers.
// 8 warps, warp tile 64x32 (4 m-tiles x 4 n-tiles of m16n8k16).
// 3-stage cp.async pipeline; stage buffers are the pre-swizzled 16KB blocks,
// so stage loads are plain linear 16B copies.
// ---------------------------------------------------------------------------
#define G_STAGE_BYTES 32768
#define G_SMEM_TOTAL  (3 * G_STAGE_BYTES)   // 98304

__device__ __forceinline__ void gemm_copy_stage(
    uint32_t sbuf, int it, int mt, int nt, int tid,
    const uint8_t* Ahi, const uint8_t* Alo,
    const uint8_t* Bhi, const uint8_t* Blo)
{
    const int p = it >> 4, kc = it & 15;
    const uint8_t* Asrc = (p < 2 ? Ahi : Alo) + ((size_t)(mt * 16 + kc)) * 16384;
    const uint8_t* Bsrc = (p == 1 ? Blo : Bhi) + ((size_t)(kc * 16 + nt)) * 16384;
#pragma unroll
    for (int i = 0; i < 4; ++i) {
        const int ch = tid + i * 256;
        cp_async16(sbuf + ch * 16,          Asrc + (size_t)ch * 16);
        cp_async16(sbuf + 16384 + ch * 16,  Bsrc + (size_t)ch * 16);
    }
    cp_commit();
}

__global__ __launch_bounds__(256, 2)
void gemm_bf16x3_mma_kernel(const uint8_t* __restrict__ Ahi, const uint8_t* __restrict__ Alo,
                            const uint8_t* __restrict__ Bhi, const uint8_t* __restrict__ Blo,
                            float* __restrict__ C)
{
    extern __shared__ char smem[];
    const uint32_t sb = smem_to_u32(smem);
    const int tid = threadIdx.x;
    const int wid = tid >> 5;
    const int lane = tid & 31;
    const int nt = blockIdx.x;   // 0..15  (N tile of 128)
    const int mt = blockIdx.y;   // 0..255 (M tile of 128)

    const int wm = (wid >> 2) * 64;   // warp m offset in tile
    const int wn = (wid & 3) * 32;    // warp n offset in tile

    float acc[4][4][4];
#pragma unroll
    for (int i = 0; i < 4; ++i)
#pragma unroll
        for (int j = 0; j < 4; ++j)
#pragma unroll
            for (int r = 0; r < 4; ++r) acc[i][j][r] = 0.f;

    // prefetch 3 stages
    gemm_copy_stage(sb + 0 * G_STAGE_BYTES, 0, mt, nt, tid, Ahi, Alo, Bhi, Blo);
    gemm_copy_stage(sb + 1 * G_STAGE_BYTES, 1, mt, nt, tid, Ahi, Alo, Bhi, Blo);
    gemm_copy_stage(sb + 2 * G_STAGE_BYTES, 2, mt, nt, tid, Ahi, Alo, Bhi, Blo);

    // precomputed ldmatrix lane addressing pieces
    const int lrow15 = lane & 15;     // row within 16-row tile
    const int lhalf  = lane >> 4;     // 0: k 0-7, 1: k 8-15 (16B unit select)

    for (int it = 0; it < 48; ++it) {
        if (it < 46)       cp_wait<2>();
        else if (it == 46) cp_wait<1>();
        else               cp_wait<0>();
        __syncthreads();

        const uint32_t aBase = sb + (uint32_t)(it % 3) * G_STAGE_BYTES;
        const uint32_t bBase = aBase + 16384;

#pragma unroll
        for (int kk = 0; kk < 4; ++kk) {
            const int unit = 2 * kk + lhalf;
            uint32_t a[4][4];
            uint32_t b[4][2];
#pragma unroll
            for (int mi = 0; mi < 4; ++mi) {
                const int row = wm + mi * 16 + lrow15;
                const uint32_t addr = aBase + row * 128 + ((unit ^ (row & 7)) << 4);
                ldmatrix_x4(a[mi][0], a[mi][1], a[mi][2], a[mi][3], addr);
            }
#pragma unroll
            for (int j = 0; j < 2; ++j) {
                const int row = wn + j * 16 + lrow15;
                const uint32_t addr = bBase + row * 128 + ((unit ^ (row & 7)) << 4);
                uint32_t r0, r1, r2, r3;
                ldmatrix_x4(r0, r1, r2, r3, addr);
                b[2*j][0] = r0;  b[2*j][1] = r2;      // n-tile 2j:   k0-7, k8-15
                b[2*j+1][0] = r1; b[2*j+1][1] = r3;   // n-tile 2j+1
            }
#pragma unroll
            for (int mi = 0; mi < 4; ++mi)
#pragma unroll
                for (int ni = 0; ni < 4; ++ni)
                    mma_bf16(acc[mi][ni], a[mi], b[ni]);
        }

        __syncthreads();
        if (it + 3 < 48)
            gemm_copy_stage(sb + (uint32_t)((it + 3) % 3) * G_STAGE_BYTES,
                            it + 3, mt, nt, tid, Ahi, Alo, Bhi, Blo);
    }

    // epilogue: d-frag -> C
    const int rbase = mt * 128 + wm + (lane >> 2);
    const int cbase = nt * 128 + wn + 2 * (lane & 3);
#pragma unroll
    for (int mi = 0; mi < 4; ++mi) {
#pragma unroll
        for (int ni = 0; ni < 4; ++ni) {
            const int r0 = rbase + mi * 16;
            const int c0 = cbase + ni * 8;
            float2* p0 = (float2*)(C + (size_t)r0 * K_CODE + c0);
            float2* p1 = (float2*)(C + (size_t)(r0 + 8) * K_CODE + c0);
            *p0 = make_float2(acc[mi][ni][0], acc[mi][ni][1]);
            *p1 = make_float2(acc[mi][ni][2], acc[mi][ni][3]);
        }
    }
}

// ---------------------------------------------------------------------------
// fast 2^y (degree-6 poly after round-to-nearest split); avoids MUFU cliff.
// ---------------------------------------------------------------------------
__device__ __forceinline__ float fast_exp2(float y)
{
    float r = rintf(y);
    float f = y - r;
    float p = 1.5403530e-4f;
    p = fmaf(p, f, 1.3333558e-3f);
    p = fmaf(p, f, 9.6181291e-3f);
    p = fmaf(p, f, 5.5504109e-2f);
    p = fmaf(p, f, 2.4022651e-1f);
    p = fmaf(p, f, 6.9314718e-1f);
    p = fmaf(p, f, 1.0f);
    int ei = (int)r;
    if (ei < -126) return 0.f;
    float s = __int_as_float((ei + 127) << 23);
    return p * s;
}

// ---------------------------------------------------------------------------
// Kernel 2: per-token row pass (max/candidates, softmax stats, diversity).
// ---------------------------------------------------------------------------
#define TOK_PER_CTA (M_TOK / RP_CTAS)   // 128

__global__ __launch_bounds__(256)
void row_pass_kernel(const float* __restrict__ S)
{
    const int tid = threadIdx.x;
    const int cta = blockIdx.x;
    const int lane = tid & 31;
    const int warp = tid >> 5;

    __shared__ float wm[8];
    __shared__ float ws0[8], ws1[8];
    __shared__ float bc_m, bc_s0, bc_s1;
    __shared__ int   s_cnt;
    __shared__ int   s_cidx[NCAND];

    float dreg[8];
#pragma unroll
    for (int j = 0; j < 8; ++j) dreg[j] = 0.f;
    float hsum = 0.f;

    for (int t = 0; t < TOK_PER_CTA; ++t) {
        const int tok = cta * TOK_PER_CTA + t;
        const float* row = S + (size_t)tok * K_CODE;

        float lv[8];
#pragma unroll
        for (int j = 0; j < 8; ++j) lv[j] = row[tid + j * 256];

        float m = lv[0];
#pragma unroll
        for (int j = 1; j < 8; ++j) m = fmaxf(m, lv[j]);
#pragma unroll
        for (int off = 16; off > 0; off >>= 1)
            m = fmaxf(m, __shfl_xor_sync(0xffffffffu, m, off));
        if (lane == 0) wm[warp] = m;
        __syncthreads();
        if (tid == 0) {
            float bmv = wm[0];
#pragma unroll
            for (int w = 1; w < 8; ++w) bmv = fmaxf(bmv, wm[w]);
            bc_m = bmv;
            s_cnt = 0;
        }
        __syncthreads();
        m = bc_m;

        const float thr = m - 0.01f;
#pragma unroll
        for (int j = 0; j < 8; ++j) {
            if (lv[j] >= thr) {
                int p = atomicAdd(&s_cnt, 1);
                if (p < NCAND) s_cidx[p] = tid + j * 256;
            }
        }

        const float LOG2E = 1.4426950408889634f;
        float s0 = 0.f, s1 = 0.f, ev[8];
#pragma unroll
        for (int j = 0; j < 8; ++j) {
            float y = (lv[j] - m) * LOG2E;
            float e = fast_exp2(y);
            ev[j] = e;
            s0 += e;
            s1 = fmaf(e, y, s1);
        }
#pragma unroll
        for (int off = 16; off > 0; off >>= 1) {
            s0 += __shfl_down_sync(0xffffffffu, s0, off);
            s1 += __shfl_down_sync(0xffffffffu, s1, off);
        }
        if (lane == 0) { ws0[warp] = s0; ws1[warp] = s1; }
        __syncthreads();
        if (tid == 0) {
            float t0 = 0.f, t1 = 0.f;
#pragma unroll
            for (int w = 0; w < 8; ++w) { t0 += ws0[w]; t1 += ws1[w]; }
            bc_s0 = t0; bc_s1 = t1;
        }
        __syncthreads();
        const float S0 = bc_s0;
        const float inv = 1.f / S0;

#pragma unroll
        for (int j = 0; j < 8; ++j) dreg[j] = fmaf(ev[j], inv, dreg[j]);

        const int cnt = (s_cnt < NCAND) ? s_cnt : NCAND;
        if (tid < cnt) g_cand_idx[tok][tid] = s_cidx[tid];
        if (tid == 0) {
            g_cand_cnt[tok] = cnt;
            hsum += bc_s1 * inv - log2f(S0);
        }
        __syncthreads();
    }

#pragma unroll
    for (int j = 0; j < 8; ++j)
        g_div_part[(size_t)cta * K_CODE + tid + j * 256] = dreg[j];
    if (tid == 0) g_h_part[cta] = hsum;
}

// ---------------------------------------------------------------------------
// Kernel 2b: fp64 refinement of argmax for near-tied tokens (1 warp/token).
// ---------------------------------------------------------------------------
__global__ __launch_bounds__(256)
void refine_kernel(const float* __restrict__ inputs,
                   const float* __restrict__ codebook,
                   float* __restrict__ nn_out)
{
    const int warp = threadIdx.x >> 5;
    const int lane = threadIdx.x & 31;
    const int tok = blockIdx.x * 8 + warp;

    const int cnt = g_cand_cnt[tok];
    int best = g_cand_idx[tok][0];

    if (cnt > 1) {
        const float* xr = inputs + (size_t)tok * D_DIM;
        double bv = -1e300;
        int bi = INT_MAX;
        for (int c = 0; c < cnt; ++c) {
            const int idx = g_cand_idx[tok][c];
            const float* cr = codebook + (size_t)idx * D_DIM;
            double s = 0.0;
            for (int i = lane; i < D_DIM; i += 32)
                s += (double)xr[i] * (double)cr[i];
#pragma unroll
            for (int off = 16; off > 0; off >>= 1)
                s += __shfl_down_sync(0xffffffffu, s, off);
            s = __shfl_sync(0xffffffffu, s, 0);
            if (s > bv || (s == bv && idx < bi)) { bv = s; bi = idx; }
        }
        best = bi;
    }

    if (lane == 0) {
        g_nn[tok] = best;
        nn_out[tok] = (float)best;
    }
}

// ---------------------------------------------------------------------------
// Kernel 3a: diversity reduce across the 256 per-CTA partials (16 CTAs).
// ---------------------------------------------------------------------------
__global__ __launch_bounds__(128)
void div_reduce_kernel()
{
    const int col = blockIdx.x * 128 + threadIdx.x;
    float s = 0.f;
#pragma unroll 8
    for (int c = 0; c < RP_CTAS; ++c)
        s += g_div_part[(size_t)c * K_CODE + col];
    float dv = s * (1.f / (float)M_TOK);
    float acc = dv * log2f(dv + 1e-8f);

    __shared__ float sa[128];
    sa[threadIdx.x] = acc;
    __syncthreads();
    for (int off = 64; off > 0; off >>= 1) {
        if (threadIdx.x < off) sa[threadIdx.x] += sa[threadIdx.x + off];
        __syncthreads();
    }
    if (threadIdx.x == 0) g_acc_part[blockIdx.x] = sa[0];
}

// ---------------------------------------------------------------------------
// Kernel 3b: final scalar loss.
// ---------------------------------------------------------------------------
__global__ __launch_bounds__(256)
void finalize2_kernel()
{
    const int tid = threadIdx.x;
    float h = g_h_part[tid];
    float a = (tid < 16) ? g_acc_part[tid] : 0.f;

    __shared__ float sh[256], sa[256];
    sh[tid] = h; sa[tid] = a;
    __syncthreads();
    for (int off = 128; off > 0; off >>= 1) {
        if (tid < off) { sh[tid] += sh[tid + off]; sa[tid] += sa[tid + off]; }
        __syncthreads();
    }
    if (tid == 0) {
        float h_clust = -sh[0] / (float)M_TOK;
        g_loss[0] = h_clust + sa[0];   // loss = h_clust - (-sa) = h_clust + sa
    }
}

// ---------------------------------------------------------------------------
// Kernel 4: broadcast scalar loss into the qloss region.
// ---------------------------------------------------------------------------
__global__ __launch_bounds__(256)
void fill_loss_kernel(float* __restrict__ dst)
{
    const float v = g_loss[0];
    const float4 v4 = make_float4(v, v, v, v);
    size_t i = ((size_t)blockIdx.x * blockDim.x + threadIdx.x);
    const size_t stride = (size_t)gridDim.x * blockDim.x;
    const size_t n4 = LOSS_N / 4;
    float4* d4 = (float4*)dst;
    for (; i < n4; i += stride) d4[i] = v4;
}

// ---------------------------------------------------------------------------
// Kernel 5: copy codebook into output.
// ---------------------------------------------------------------------------
__global__ __launch_bounds__(256)
void copy_cb_kernel(const float* __restrict__ src, float* __restrict__ dst)
{
    size_t i = ((size_t)blockIdx.x * blockDim.x + threadIdx.x);
    const size_t stride = (size_t)gridDim.x * blockDim.x;
    const size_t n4 = CB_N / 4;
    const float4* s4 = (const float4*)src;
    float4* d4 = (float4*)dst;
    for (; i < n4; i += stride) d4[i] = s4[i];
}

// ---------------------------------------------------------------------------
// Kernel 6: gather + center + L2-normalize + straight-through identity.
// ---------------------------------------------------------------------------
__global__ __launch_bounds__(256)
void quantize_kernel(const float* __restrict__ inputs,
                     const float* __restrict__ codebook,
                     float* __restrict__ qout)
{
    const int warp = threadIdx.x >> 5;
    const int lane = threadIdx.x & 31;
    const int tok = blockIdx.x * 8 + warp;
    const int idx = g_nn[tok];
    const float* row = codebook + (size_t)idx * D_DIM;

    float4 x[8];
    float sum = 0.f;
#pragma unroll
    for (int c = 0; c < 8; ++c) {
        x[c] = *(const float4*)(row + c * 128 + lane * 4);
        sum += x[c].x + x[c].y + x[c].z + x[c].w;
    }
#pragma unroll
    for (int off = 16; off > 0; off >>= 1)
        sum += __shfl_xor_sync(0xffffffffu, sum, off);
    const float mean = sum * (1.f / (float)D_DIM);

    float ss = 0.f;
#pragma unroll
    for (int c = 0; c < 8; ++c) {
        x[c].x -= mean; x[c].y -= mean; x[c].z -= mean; x[c].w -= mean;
        ss += x[c].x * x[c].x + x[c].y * x[c].y + x[c].z * x[c].z + x[c].w * x[c].w;
    }
#pragma unroll
    for (int off = 16; off > 0; off >>= 1)
        ss += __shfl_xor_sync(0xffffffffu, ss, off);
    const float invn = 1.f / sqrtf(ss);

    const float* xin = inputs + (size_t)tok * D_DIM;
    float* out = qout + (size_t)tok * D_DIM;
#pragma unroll
    for (int c = 0; c < 8; ++c) {
        float4 iv = *(const float4*)(xin + c * 128 + lane * 4);
        float4 v;
        v.x = iv.x + (x[c].x * invn - iv.x);
        v.y = iv.y + (x[c].y * invn - iv.y);
        v.z = iv.z + (x[c].z * invn - iv.z);
        v.w = iv.w + (x[c].w * invn - iv.w);
        *(float4*)(out + c * 128 + lane * 4) = v;
    }
}

// ---------------------------------------------------------------------------
extern "C" void kernel_launch(void* const* d_in, const int* in_sizes, int n_in,
                              void* d_out, int out_size)
{
    const float* inputs   = (const float*)d_in[0];
    const float* codebook = (const float*)d_in[1];
    float* out = (float*)d_out;

    float *logits;
    uint4 *Ahi, *Alo, *Bhi, *Blo;
    cudaGetSymbolAddress((void**)&logits, g_logits);
    cudaGetSymbolAddress((void**)&Ahi, g_Ahi);
    cudaGetSymbolAddress((void**)&Alo, g_Alo);
    cudaGetSymbolAddress((void**)&Bhi, g_Bhi);
    cudaGetSymbolAddress((void**)&Blo, g_Blo);

    // 0) split fp32 -> bf16 hi/lo, pre-tiled + swizzled
    split_kernel<<<(M_TOK * 128) / 256, 256>>>(inputs, Ahi, Alo, M_TOK * 128, 16, 1);
    split_kernel<<<(K_CODE * 128) / 256, 256>>>(codebook, Bhi, Blo, K_CODE * 128, 1, 16);

    // 1) bf16 3-split similarity GEMM (warp mma.sync path)
    cudaFuncSetAttribute(gemm_bf16x3_mma_kernel,
                         cudaFuncAttributeMaxDynamicSharedMemorySize, G_SMEM_TOTAL);
    {
        dim3 grid(K_CODE / 128, M_TOK / 128);   // (16, 256)
        gemm_bf16x3_mma_kernel<<<grid, 256, G_SMEM_TOTAL>>>(
            (const uint8_t*)Ahi, (const uint8_t*)Alo,
            (const uint8_t*)Bhi, (const uint8_t*)Blo, logits);
    }

    // 2) row pass
    row_pass_kernel<<<RP_CTAS, 256>>>(logits);
    // 2b) fp64 refine of near-tied argmax -> final nn_idx
    refine_kernel<<<M_TOK / 8, 256>>>(inputs, codebook, out + NN_OFF);
    // 3) loss reduction
    div_reduce_kernel<<<16, 128>>>();
    finalize2_kernel<<<1, 256>>>();
    // 4) broadcast loss
    fill_loss_kernel<<<8192, 256>>>(out + LOSS_OFF);
    // 5) codebook passthrough
    copy_cb_kernel<<<2048, 256>>>(codebook, out + CB_OFF);
    // 6) quantized rows
    quantize_kernel<<<M_TOK / 8, 256>>>(inputs, codebook, out + QUANT_OFF);
}

// round 12
// speedup vs baseline: 2.4847x; 1.0626x over previous
#include <cuda_runtime.h>
#include <cuda_bf16.h>
#include <cstdint>
#include <cstddef>
#include <climits>

// ---------------------------------------------------------------------------
// Problem shape (fixed by the dataset)
//   inputs:   [16, 2048, 1024] f32  -> M = 32768 tokens, D = 1024
//   codebook: [2048, 1024]     f32  -> K = 2048 codes
// Outputs concatenated (f32):
//   quantized  [32768,1024]  @ 0
//   qloss      [32768,2048]  @ 33554432   (scalar broadcast)
//   nn_idx     [32768]       @ 100663296  (as float)
//   codebook   [2048,1024]   @ 100696064
// ---------------------------------------------------------------------------
#define M_TOK   32768
#define K_CODE  2048
#define D_DIM   1024

#define QUANT_OFF 0
#define LOSS_OFF  33554432
#define NN_OFF    100663296
#define CB_OFF    100696064
#define LOSS_N    67108864
#define CB_N      2097152

#define NCAND 8

// ------------------------- scratch (device globals) ------------------------
__device__ float g_logits[(size_t)M_TOK * K_CODE];   // 256 MiB

#define RP_WARPS 4096          // 512 CTAs x 8 warps, 8 tokens per warp
__device__ float g_div_part[(size_t)RP_WARPS * K_CODE];   // 32 MiB per-warp partials
__device__ float g_h_part[RP_WARPS];
__device__ float g_acc_part[16];
__device__ int   g_nn[M_TOK];
__device__ float g_loss[1];
__device__ int   g_cand_cnt[M_TOK];
__device__ int   g_cand_idx[M_TOK][NCAND];

// bf16 split operands, pre-tiled + pre-SW128-swizzled into 16KB blocks of
// [128 rows x 64 cols bf16] (= 128 rows x 128B).
//   A blocks ordered [m_tile (256)][k_chunk (16)]
//   B blocks ordered [k_chunk (16)][n_block (16)]
__device__ uint4 g_Ahi[(size_t)M_TOK * D_DIM / 8];   // 64 MiB
__device__ uint4 g_Alo[(size_t)M_TOK * D_DIM / 8];   // 64 MiB
__device__ uint4 g_Bhi[(size_t)K_CODE * D_DIM / 8];  // 4 MiB
__device__ uint4 g_Blo[(size_t)K_CODE * D_DIM / 8];  // 4 MiB (unused by GEMM now)

// ------------------------- PTX helpers ---------------------------
__device__ __forceinline__ uint32_t smem_to_u32(const void* p) {
    uint32_t a;
    asm("{ .reg .u64 t; cvta.to.shared.u64 t, %1; cvt.u32.u64 %0, t; }" : "=r"(a) : "l"(p));
    return a;
}

__device__ __forceinline__ void cp_async16(uint32_t dst, const void* src) {
    asm volatile("cp.async.cg.shared.global [%0], [%1], 16;" :: "r"(dst), "l"(src) : "memory");
}
__device__ __forceinline__ void cp_commit() {
    asm volatile("cp.async.commit_group;" ::: "memory");
}
template <int N>
__device__ __forceinline__ void cp_wait() {
    asm volatile("cp.async.wait_group %0;" :: "n"(N) : "memory");
}

__device__ __forceinline__ void ldmatrix_x4(uint32_t& r0, uint32_t& r1,
                                            uint32_t& r2, uint32_t& r3, uint32_t addr) {
    asm volatile("ldmatrix.sync.aligned.m8n8.x4.shared.b16 {%0,%1,%2,%3}, [%4];"
                 : "=r"(r0), "=r"(r1), "=r"(r2), "=r"(r3) : "r"(addr));
}

__device__ __forceinline__ void mma_bf16(float* c, const uint32_t* a, const uint32_t* b) {
    asm volatile(
        "mma.sync.aligned.m16n8k16.row.col.f32.bf16.bf16.f32 "
        "{%0,%1,%2,%3}, {%4,%5,%6,%7}, {%8,%9}, {%0,%1,%2,%3};"
        : "+f"(c[0]), "+f"(c[1]), "+f"(c[2]), "+f"(c[3])
        : "r"(a[0]), "r"(a[1]), "r"(a[2]), "r"(a[3]), "r"(b[0]), "r"(b[1]));
}

// ---------------------------------------------------------------------------
// Kernel 0: fp32 -> (bf16 hi, bf16 lo), tiled into 16KB SW128-swizzled blocks.
// ---------------------------------------------------------------------------
__global__ __launch_bounds__(256)
void split_kernel(const float* __restrict__ src,
                  uint4* __restrict__ hi, uint4* __restrict__ lo,
                  int nchunks, int tileStride, int kcStride)
{
    int i = blockIdx.x * blockDim.x + threadIdx.x;
    if (i >= nchunks) return;
    const int c8   = i & 127;
    const int row  = i >> 7;
    const int kc   = c8 >> 3;
    const int g    = c8 & 7;
    const int tile = row >> 7;
    const int r    = row & 127;

    const size_t blk = (size_t)tile * tileStride + (size_t)kc * kcStride;
    uint32_t off = r * 128 + g * 16;
    off ^= (off >> 3) & 0x70;                     // SW128 swizzle
    const size_t dst = blk * 1024 + (off >> 4);

    const float4* s4 = (const float4*)(src + ((size_t)row << 10) + (c8 << 3));
    float4 x0 = s4[0], x1 = s4[1];
    float xs[8] = {x0.x, x0.y, x0.z, x0.w, x1.x, x1.y, x1.z, x1.w};
    uint32_t hw[4], lw[4];
#pragma unroll
    for (int j = 0; j < 4; ++j) {
        float a = xs[2*j], b = xs[2*j+1];
        __nv_bfloat16 h0 = __float2bfloat16_rn(a);
        __nv_bfloat16 h1 = __float2bfloat16_rn(b);
        __nv_bfloat16 l0 = __float2bfloat16_rn(a - __bfloat162float(h0));
        __nv_bfloat16 l1 = __float2bfloat16_rn(b - __bfloat162float(h1));
        hw[j] = (uint32_t)__bfloat16_as_ushort(h0) | ((uint32_t)__bfloat16_as_ushort(h1) << 16);
        lw[j] = (uint32_t)__bfloat16_as_ushort(l0) | ((uint32_t)__bfloat16_as_ushort(l1) << 16);
    }
    hi[dst] = make_uint4(hw[0], hw[1], hw[2], hw[3]);
    lo[dst] = make_uint4(lw[0], lw[1], lw[2], lw[3]);
}

// ---------------------------------------------------------------------------
// Kernel 1: bf16 2-split GEMM via mma.sync:  C ~= (Ahi + Alo) * Bhi^T.
// (Dropped A*Blo term: logit abs error sigma ~0.035; argmax protected by the
//  0.4 candidate threshold + fp64 refine; loss error ~1e-3 abs << budget.)
// CTA tile 128(M) x 256(N), BK=64 per stage; 32 stages = 2 passes x 16 kc.
// 16 warps (512 thr), warp tile 32x64 (2 m-frags x 8 n-frags).
// 3-stage cp.async pipeline over pre-swizzled 16KB blocks (linear copies).
// ---------------------------------------------------------------------------
#define G_STAGE_BYTES 49152
#define G_SMEM_TOTAL  (3 * G_STAGE_BYTES)   // 147456

__device__ __forceinline__ void gemm_copy_stage(
    uint32_t sbuf, int it, int mt, int nt, int tid,
    const uint8_t* Ahi, const uint8_t* Alo, const uint8_t* Bhi)
{
    const int p = it >> 4, kc = it & 15;
    const uint8_t* Asrc = (p == 0 ? Ahi : Alo) + ((size_t)(mt * 16 + kc)) * 16384;
    const uint8_t* Bsrc = Bhi + ((size_t)(kc * 16 + 2 * nt)) * 16384;   // 2 consecutive blocks
#pragma unroll
    for (int i = 0; i < 2; ++i) {
        const int ch = tid + i * 512;
        cp_async16(sbuf + ch * 16, Asrc + (size_t)ch * 16);
    }
#pragma unroll
    for (int i = 0; i < 4; ++i) {
        const int ch = tid + i * 512;
        cp_async16(sbuf + 16384 + ch * 16, Bsrc + (size_t)ch * 16);
    }
    cp_commit();
}

__global__ __launch_bounds__(512, 1)
void gemm_bf16x2_mma_kernel(const uint8_t* __restrict__ Ahi, const uint8_t* __restrict__ Alo,
                            const uint8_t* __restrict__ Bhi,
                            float* __restrict__ C)
{
    extern __shared__ char smem[];
    const uint32_t sb = smem_to_u32(smem);
    const int tid = threadIdx.x;
    const int wid = tid >> 5;
    const int lane = tid & 31;
    const int nt = blockIdx.x;   // 0..7   (N tile of 256)
    const int mt = blockIdx.y;   // 0..255 (M tile of 128)

    const int wm = (wid >> 2) * 32;   // warp m offset (0..96)
    const int wn = (wid & 3) * 64;    // warp n offset (0..192)

    float acc[2][8][4];
#pragma unroll
    for (int i = 0; i < 2; ++i)
#pragma unroll
        for (int j = 0; j < 8; ++j)
#pragma unroll
            for (int r = 0; r < 4; ++r) acc[i][j][r] = 0.f;

    gemm_copy_stage(sb + 0 * G_STAGE_BYTES, 0, mt, nt, tid, Ahi, Alo, Bhi);
    gemm_copy_stage(sb + 1 * G_STAGE_BYTES, 1, mt, nt, tid, Ahi, Alo, Bhi);
    gemm_copy_stage(sb + 2 * G_STAGE_BYTES, 2, mt, nt, tid, Ahi, Alo, Bhi);

    const int lrow15 = lane & 15;
    const int lhalf  = lane >> 4;

    for (int it = 0; it < 32; ++it) {
        if (it < 30)       cp_wait<2>();
        else if (it == 30) cp_wait<1>();
        else               cp_wait<0>();
        __syncthreads();

        const uint32_t aBase = sb + (uint32_t)(it % 3) * G_STAGE_BYTES;
        const uint32_t bBase = aBase + 16384;

#pragma unroll
        for (int kk = 0; kk < 4; ++kk) {
            const int unit = 2 * kk + lhalf;
            uint32_t a[2][4];
            uint32_t b[8][2];
#pragma unroll
            for (int mi = 0; mi < 2; ++mi) {
                const int row = wm + mi * 16 + lrow15;
                const uint32_t addr = aBase + row * 128 + ((unit ^ (row & 7)) << 4);
                ldmatrix_x4(a[mi][0], a[mi][1], a[mi][2], a[mi][3], addr);
            }
#pragma unroll
            for (int j = 0; j < 4; ++j) {
                const int row = wn + j * 16 + lrow15;
                const uint32_t addr = bBase + row * 128 + ((unit ^ (row & 7)) << 4);
                uint32_t r0, r1, r2, r3;
                ldmatrix_x4(r0, r1, r2, r3, addr);
                b[2*j][0]   = r0; b[2*j][1]   = r2;
                b[2*j+1][0] = r1; b[2*j+1][1] = r3;
            }
#pragma unroll
            for (int mi = 0; mi < 2; ++mi)
#pragma unroll
                for (int ni = 0; ni < 8; ++ni)
                    mma_bf16(acc[mi][ni], a[mi], b[ni]);
        }

        __syncthreads();
        if (it + 3 < 32)
            gemm_copy_stage(sb + (uint32_t)((it + 3) % 3) * G_STAGE_BYTES,
                            it + 3, mt, nt, tid, Ahi, Alo, Bhi);
    }

    const int rbase = mt * 128 + wm + (lane >> 2);
    const int cbase = nt * 256 + wn + 2 * (lane & 3);
#pragma unroll
    for (int mi = 0; mi < 2; ++mi) {
#pragma unroll
        for (int ni = 0; ni < 8; ++ni) {
            const int r0 = rbase + mi * 16;
            const int c0 = cbase + ni * 8;
            float2* p0 = (float2*)(C + (size_t)r0 * K_CODE + c0);
            float2* p1 = (float2*)(C + (size_t)(r0 + 8) * K_CODE + c0);
            *p0 = make_float2(acc[mi][ni][0], acc[mi][ni][1]);
            *p1 = make_float2(acc[mi][ni][2], acc[mi][ni][3]);
        }
    }
}

// ---------------------------------------------------------------------------
// fast 2^y (degree-6 poly after round-to-nearest split); avoids MUFU cliff.
// ---------------------------------------------------------------------------
__device__ __forceinline__ float fast_exp2(float y)
{
    float r = rintf(y);
    float f = y - r;
    float p = 1.5403530e-4f;
    p = fmaf(p, f, 1.3333558e-3f);
    p = fmaf(p, f, 9.6181291e-3f);
    p = fmaf(p, f, 5.5504109e-2f);
    p = fmaf(p, f, 2.4022651e-1f);
    p = fmaf(p, f, 6.9314718e-1f);
    p = fmaf(p, f, 1.0f);
    int ei = (int)r;
    if (ei < -126) return 0.f;
    float s = __int_as_float((ei + 127) << 23);
    return p * s;
}

// ---------------------------------------------------------------------------
// Kernel 2: row pass, warp-per-token (no block syncs).
// 512 CTAs x 8 warps, 8 tokens/warp. Lane holds 64 logits in registers;
// warp-shuffle reductions; per-warp diversity partials written coalesced.
// Candidate threshold 0.4 (covers the 2-split GEMM logit error).
// ---------------------------------------------------------------------------
__global__ __launch_bounds__(256)
void row_pass_kernel(const float* __restrict__ S)
{
    const int lane = threadIdx.x & 31;
    const int warp = threadIdx.x >> 5;
    const int gw = blockIdx.x * 8 + warp;        // global warp id, 0..4095

    float dreg[64];
#pragma unroll
    for (int j = 0; j < 64; ++j) dreg[j] = 0.f;
    float hsum = 0.f;

    for (int t = 0; t < 8; ++t) {
        const int tok = gw * 8 + t;
        const float4* row4 = (const float4*)(S + (size_t)tok * K_CODE);

        float v[64];
#pragma unroll
        for (int jj = 0; jj < 16; ++jj) {
            float4 x = row4[lane + 32 * jj];
            v[4*jj+0] = x.x; v[4*jj+1] = x.y; v[4*jj+2] = x.z; v[4*jj+3] = x.w;
        }

        // ---- max (warp) ----
        float m = v[0];
#pragma unroll
        for (int j = 1; j < 64; ++j) m = fmaxf(m, v[j]);
#pragma unroll
        for (int off = 16; off > 0; off >>= 1)
            m = fmaxf(m, __shfl_xor_sync(0xffffffffu, m, off));

        // ---- candidates within 0.4 of max ----
        const float thr = m - 0.4f;
        int cnt_l = 0;
#pragma unroll
        for (int j = 0; j < 64; ++j) cnt_l += (v[j] >= thr) ? 1 : 0;
        int pre = cnt_l;
#pragma unroll
        for (int off = 1; off < 32; off <<= 1) {
            int n = __shfl_up_sync(0xffffffffu, pre, off);
            if (lane >= off) pre += n;
        }
        const int total = __shfl_sync(0xffffffffu, pre, 31);
        int slot = pre - cnt_l;   // exclusive prefix
        if (cnt_l) {
#pragma unroll
            for (int j = 0; j < 64; ++j) {
                if (v[j] >= thr) {
                    if (slot < NCAND)
                        g_cand_idx[tok][slot] = 4 * lane + 128 * (j >> 2) + (j & 3);
                    ++slot;
                }
            }
        }
        if (lane == 0) g_cand_cnt[tok] = (total < NCAND) ? total : NCAND;

        // ---- softmax stats ----
        const float LOG2E = 1.4426950408889634f;
        float s0 = 0.f, s1 = 0.f;
#pragma unroll
        for (int j = 0; j < 64; ++j) {
            float y = (v[j] - m) * LOG2E;
            float e = fast_exp2(y);
            v[j] = e;
            s0 += e;
            s1 = fmaf(e, y, s1);
        }
#pragma unroll
        for (int off = 16; off > 0; off >>= 1) {
            s0 += __shfl_xor_sync(0xffffffffu, s0, off);
            s1 += __shfl_xor_sync(0xffffffffu, s1, off);
        }
        const float inv = 1.f / s0;
#pragma unroll
        for (int j = 0; j < 64; ++j) dreg[j] = fmaf(v[j], inv, dreg[j]);
        hsum += s1 * inv - log2f(s0);
    }

    // per-warp diversity partial (coalesced float4 stores)
    float4* dp = (float4*)(g_div_part + (size_t)gw * K_CODE);
#pragma unroll
    for (int jj = 0; jj < 16; ++jj)
        dp[lane + 32 * jj] = make_float4(dreg[4*jj], dreg[4*jj+1], dreg[4*jj+2], dreg[4*jj+3]);
    if (lane == 0) g_h_part[gw] = hsum;
}

// ---------------------------------------------------------------------------
// Kernel 2b: fp64 refinement of argmax among candidates (1 warp/token).
// ---------------------------------------------------------------------------
__global__ __launch_bounds__(256)
void refine_kernel(const float* __restrict__ inputs,
                   const float* __restrict__ codebook,
                   float* __restrict__ nn_out)
{
    const int warp = threadIdx.x >> 5;
    const int lane = threadIdx.x & 31;
    const int tok = blockIdx.x * 8 + warp;

    const int cnt = g_cand_cnt[tok];
    int best = g_cand_idx[tok][0];

    if (cnt > 1) {
        const float* xr = inputs + (size_t)tok * D_DIM;
        double bv = -1e300;
        int bi = INT_MAX;
        for (int c = 0; c < cnt; ++c) {
            const int idx = g_cand_idx[tok][c];
            const float* cr = codebook + (size_t)idx * D_DIM;
            double s = 0.0;
            for (int i = lane; i < D_DIM; i += 32)
                s += (double)xr[i] * (double)cr[i];
#pragma unroll
            for (int off = 16; off > 0; off >>= 1)
                s += __shfl_down_sync(0xffffffffu, s, off);
            s = __shfl_sync(0xffffffffu, s, 0);
            if (s > bv || (s == bv && idx < bi)) { bv = s; bi = idx; }
        }
        best = bi;
    }

    if (lane == 0) {
        g_nn[tok] = best;
        nn_out[tok] = (float)best;
    }
}

// ---------------------------------------------------------------------------
// Kernel 3a: diversity reduce across the 4096 per-warp partials (16 CTAs).
// ---------------------------------------------------------------------------
__global__ __launch_bounds__(128)
void div_reduce_kernel()
{
    const int col = blockIdx.x * 128 + threadIdx.x;
    float s = 0.f;
#pragma unroll 8
    for (int w = 0; w < RP_WARPS; ++w)
        s += g_div_part[(size_t)w * K_CODE + col];
    float dv = s * (1.f / (float)M_TOK);
    float acc = dv * log2f(dv + 1e-8f);

    __shared__ float sa[128];
    sa[threadIdx.x] = acc;
    __syncthreads();
    for (int off = 64; off > 0; off >>= 1) {
        if (threadIdx.x < off) sa[threadIdx.x] += sa[threadIdx.x + off];
        __syncthreads();
    }
    if (threadIdx.x == 0) g_acc_part[blockIdx.x] = sa[0];
}

// ---------------------------------------------------------------------------
// Kernel 3b: final scalar loss.
// ---------------------------------------------------------------------------
__global__ __launch_bounds__(256)
void finalize2_kernel()
{
    const int tid = threadIdx.x;
    float h = 0.f;
#pragma unroll
    for (int i = 0; i < RP_WARPS / 256; ++i)     // 16 per thread
        h += g_h_part[tid * (RP_WARPS / 256) + i];
    float a = (tid < 16) ? g_acc_part[tid] : 0.f;

    __shared__ float sh[256], sa[256];
    sh[tid] = h; sa[tid] = a;
    __syncthreads();
    for (int off = 128; off > 0; off >>= 1) {
        if (tid < off) { sh[tid] += sh[tid + off]; sa[tid] += sa[tid + off]; }
        __syncthreads();
    }
    if (tid == 0) {
        float h_clust = -sh[0] / (float)M_TOK;
        g_loss[0] = h_clust + sa[0];   // loss = h_clust - (-sa) = h_clust + sa
    }
}

// ---------------------------------------------------------------------------
// Kernel 4: broadcast scalar loss into the qloss region.
// ---------------------------------------------------------------------------
__global__ __launch_bounds__(256)
void fill_loss_kernel(float* __restrict__ dst)
{
    const float v = g_loss[0];
    const float4 v4 = make_float4(v, v, v, v);
    size_t i = ((size_t)blockIdx.x * blockDim.x + threadIdx.x);
    const size_t stride = (size_t)gridDim.x * blockDim.x;
    const size_t n4 = LOSS_N / 4;
    float4* d4 = (float4*)dst;
    for (; i < n4; i += stride) d4[i] = v4;
}

// ---------------------------------------------------------------------------
// Kernel 5: copy codebook into output.
// ---------------------------------------------------------------------------
__global__ __launch_bounds__(256)
void copy_cb_kernel(const float* __restrict__ src, float* __restrict__ dst)
{
    size_t i = ((size_t)blockIdx.x * blockDim.x + threadIdx.x);
    const size_t stride = (size_t)gridDim.x * blockDim.x;
    const size_t n4 = CB_N / 4;
    const float4* s4 = (const float4*)src;
    float4* d4 = (float4*)dst;
    for (; i < n4; i += stride) d4[i] = s4[i];
}

// ---------------------------------------------------------------------------
// Kernel 6: gather + center + L2-normalize + straight-through identity.
// ---------------------------------------------------------------------------
__global__ __launch_bounds__(256)
void quantize_kernel(const float* __restrict__ inputs,
                     const float* __restrict__ codebook,
                     float* __restrict__ qout)
{
    const int warp = threadIdx.x >> 5;
    const int lane = threadIdx.x & 31;
    const int tok = blockIdx.x * 8 + warp;
    const int idx = g_nn[tok];
    const float* row = codebook + (size_t)idx * D_DIM;

    float4 x[8];
    float sum = 0.f;
#pragma unroll
    for (int c = 0; c < 8; ++c) {
        x[c] = *(const float4*)(row + c * 128 + lane * 4);
        sum += x[c].x + x[c].y + x[c].z + x[c].w;
    }
#pragma unroll
    for (int off = 16; off > 0; off >>= 1)
        sum += __shfl_xor_sync(0xffffffffu, sum, off);
    const float mean = sum * (1.f / (float)D_DIM);

    float ss = 0.f;
#pragma unroll
    for (int c = 0; c < 8; ++c) {
        x[c].x -= mean; x[c].y -= mean; x[c].z -= mean; x[c].w -= mean;
        ss += x[c].x * x[c].x + x[c].y * x[c].y + x[c].z * x[c].z + x[c].w * x[c].w;
    }
#pragma unroll
    for (int off = 16; off > 0; off >>= 1)
        ss += __shfl_xor_sync(0xffffffffu, ss, off);
    const float invn = 1.f / sqrtf(ss);

    const float* xin = inputs + (size_t)tok * D_DIM;
    float* out = qout + (size_t)tok * D_DIM;
#pragma unroll
    for (int c = 0; c < 8; ++c) {
        float4 iv = *(const float4*)(xin + c * 128 + lane * 4);
        float4 v;
        v.x = iv.x + (x[c].x * invn - iv.x);
        v.y = iv.y + (x[c].y * invn - iv.y);
        v.z = iv.z + (x[c].z * invn - iv.z);
        v.w = iv.w + (x[c].w * invn - iv.w);
        *(float4*)(out + c * 128 + lane * 4) = v;
    }
}

// ---------------------------------------------------------------------------
extern "C" void kernel_launch(void* const* d_in, const int* in_sizes, int n_in,
                              void* d_out, int out_size)
{
    const float* inputs   = (const float*)d_in[0];
    const float* codebook = (const float*)d_in[1];
    float* out = (float*)d_out;

    float *logits;
    uint4 *Ahi, *Alo, *Bhi, *Blo;
    cudaGetSymbolAddress((void**)&logits, g_logits);
    cudaGetSymbolAddress((void**)&Ahi, g_Ahi);
    cudaGetSymbolAddress((void**)&Alo, g_Alo);
    cudaGetSymbolAddress((void**)&Bhi, g_Bhi);
    cudaGetSymbolAddress((void**)&Blo, g_Blo);

    // 0) split fp32 -> bf16 hi/lo, pre-tiled + swizzled
    split_kernel<<<(M_TOK * 128) / 256, 256>>>(inputs, Ahi, Alo, M_TOK * 128, 16, 1);
    split_kernel<<<(K_CODE * 128) / 256, 256>>>(codebook, Bhi, Blo, K_CODE * 128, 1, 16);

    // 1) bf16 2-split similarity GEMM (mma.sync), tile 128x256
    cudaFuncSetAttribute(gemm_bf16x2_mma_kernel,
                         cudaFuncAttributeMaxDynamicSharedMemorySize, G_SMEM_TOTAL);
    {
        dim3 grid(K_CODE / 256, M_TOK / 128);   // (8, 256)
        gemm_bf16x2_mma_kernel<<<grid, 512, G_SMEM_TOTAL>>>(
            (const uint8_t*)Ahi, (const uint8_t*)Alo, (const uint8_t*)Bhi, logits);
    }

    // 2) row pass (warp-per-token)
    row_pass_kernel<<<RP_WARPS / 8, 256>>>(logits);
    // 2b) fp64 refine of near-tied argmax -> final nn_idx
    refine_kernel<<<M_TOK / 8, 256>>>(inputs, codebook, out + NN_OFF);
    // 3) loss reduction
    div_reduce_kernel<<<16, 128>>>();
    finalize2_kernel<<<1, 256>>>();
    // 4) broadcast loss
    fill_loss_kernel<<<8192, 256>>>(out + LOSS_OFF);
    // 5) codebook passthrough
    copy_cb_kernel<<<2048, 256>>>(codebook, out + CB_OFF);
    // 6) quantized rows
    quantize_kernel<<<M_TOK / 8, 256>>>(inputs, codebook, out + QUANT_OFF);
}

// round 13
// speedup vs baseline: 2.7331x; 1.1000x over previous
#include <cuda_runtime.h>
#include <cuda_bf16.h>
#include <cstdint>
#include <cstddef>
#include <climits>

// ---------------------------------------------------------------------------
// Problem shape (fixed by the dataset)
//   inputs:   [16, 2048, 1024] f32  -> M = 32768 tokens, D = 1024
//   codebook: [2048, 1024]     f32  -> K = 2048 codes
// Outputs concatenated (f32):
//   quantized  [32768,1024]  @ 0
//   qloss      [32768,2048]  @ 33554432   (scalar broadcast)
//   nn_idx     [32768]       @ 100663296  (as float)
//   codebook   [2048,1024]   @ 100696064
// ---------------------------------------------------------------------------
#define M_TOK   32768
#define K_CODE  2048
#define D_DIM   1024

#define QUANT_OFF 0
#define LOSS_OFF  33554432
#define NN_OFF    100663296
#define CB_OFF    100696064
#define LOSS_N    67108864
#define CB_N      2097152

#define NCAND 8

// ------------------------- scratch (device globals) ------------------------
__device__ float g_logits[(size_t)M_TOK * K_CODE];   // 256 MiB

#define RP_WARPS 4096          // 512 CTAs x 8 warps, 8 tokens per warp
__device__ float g_div_part[(size_t)RP_WARPS * K_CODE];   // 32 MiB per-warp partials
__device__ float g_h_part[RP_WARPS];
__device__ float g_acc_part[16];
__device__ int   g_nn[M_TOK];
__device__ float g_loss[1];
__device__ int   g_cand_cnt[M_TOK];
__device__ int   g_cand_idx[M_TOK][NCAND];

// bf16 split operands, pre-tiled + pre-SW128-swizzled into 16KB blocks of
// [128 rows x 64 cols bf16] (= 128 rows x 128B).
//   A blocks ordered [m_tile (256)][k_chunk (16)]
//   B blocks ordered [k_chunk (16)][n_block (16)]
__device__ uint4 g_Ahi[(size_t)M_TOK * D_DIM / 8];   // 64 MiB
__device__ uint4 g_Alo[(size_t)M_TOK * D_DIM / 8];   // 64 MiB
__device__ uint4 g_Bhi[(size_t)K_CODE * D_DIM / 8];  // 4 MiB
__device__ uint4 g_Blo[(size_t)K_CODE * D_DIM / 8];  // 4 MiB (unused by GEMM)

// ------------------------- PTX helpers ---------------------------
__device__ __forceinline__ uint32_t smem_to_u32(const void* p) {
    uint32_t a;
    asm("{ .reg .u64 t; cvta.to.shared.u64 t, %1; cvt.u32.u64 %0, t; }" : "=r"(a) : "l"(p));
    return a;
}

__device__ __forceinline__ void cp_async16(uint32_t dst, const void* src) {
    asm volatile("cp.async.cg.shared.global [%0], [%1], 16;" :: "r"(dst), "l"(src) : "memory");
}
__device__ __forceinline__ void cp_commit() {
    asm volatile("cp.async.commit_group;" ::: "memory");
}
template <int N>
__device__ __forceinline__ void cp_wait() {
    asm volatile("cp.async.wait_group %0;" :: "n"(N) : "memory");
}

__device__ __forceinline__ void ldmatrix_x4(uint32_t& r0, uint32_t& r1,
                                            uint32_t& r2, uint32_t& r3, uint32_t addr) {
    asm volatile("ldmatrix.sync.aligned.m8n8.x4.shared.b16 {%0,%1,%2,%3}, [%4];"
                 : "=r"(r0), "=r"(r1), "=r"(r2), "=r"(r3) : "r"(addr));
}

__device__ __forceinline__ void mma_bf16(float* c, const uint32_t* a, const uint32_t* b) {
    asm volatile(
        "mma.sync.aligned.m16n8k16.row.col.f32.bf16.bf16.f32 "
        "{%0,%1,%2,%3}, {%4,%5,%6,%7}, {%8,%9}, {%0,%1,%2,%3};"
        : "+f"(c[0]), "+f"(c[1]), "+f"(c[2]), "+f"(c[3])
        : "r"(a[0]), "r"(a[1]), "r"(a[2]), "r"(a[3]), "r"(b[0]), "r"(b[1]));
}

// ---------------------------------------------------------------------------
// Kernel 0: fp32 -> (bf16 hi, bf16 lo), tiled into 16KB SW128-swizzled blocks.
// ---------------------------------------------------------------------------
__global__ __launch_bounds__(256)
void split_kernel(const float* __restrict__ src,
                  uint4* __restrict__ hi, uint4* __restrict__ lo,
                  int nchunks, int tileStride, int kcStride)
{
    int i = blockIdx.x * blockDim.x + threadIdx.x;
    if (i >= nchunks) return;
    const int c8   = i & 127;
    const int row  = i >> 7;
    const int kc   = c8 >> 3;
    const int g    = c8 & 7;
    const int tile = row >> 7;
    const int r    = row & 127;

    const size_t blk = (size_t)tile * tileStride + (size_t)kc * kcStride;
    uint32_t off = r * 128 + g * 16;
    off ^= (off >> 3) & 0x70;                     // SW128 swizzle
    const size_t dst = blk * 1024 + (off >> 4);

    const float4* s4 = (const float4*)(src + ((size_t)row << 10) + (c8 << 3));
    float4 x0 = s4[0], x1 = s4[1];
    float xs[8] = {x0.x, x0.y, x0.z, x0.w, x1.x, x1.y, x1.z, x1.w};
    uint32_t hw[4], lw[4];
#pragma unroll
    for (int j = 0; j < 4; ++j) {
        float a = xs[2*j], b = xs[2*j+1];
        __nv_bfloat16 h0 = __float2bfloat16_rn(a);
        __nv_bfloat16 h1 = __float2bfloat16_rn(b);
        __nv_bfloat16 l0 = __float2bfloat16_rn(a - __bfloat162float(h0));
        __nv_bfloat16 l1 = __float2bfloat16_rn(b - __bfloat162float(h1));
        hw[j] = (uint32_t)__bfloat16_as_ushort(h0) | ((uint32_t)__bfloat16_as_ushort(h1) << 16);
        lw[j] = (uint32_t)__bfloat16_as_ushort(l0) | ((uint32_t)__bfloat16_as_ushort(l1) << 16);
    }
    hi[dst] = make_uint4(hw[0], hw[1], hw[2], hw[3]);
    lo[dst] = make_uint4(lw[0], lw[1], lw[2], lw[3]);
}

// ---------------------------------------------------------------------------
// Kernel 1: bf16 2-split GEMM, hi/lo FUSED per stage:
//   C = (Ahi + Alo) * Bhi^T, both products accumulated into the same regs,
//   sharing each loaded B fragment (2 MMAs per B frag).
// CTA tile 128(M) x 128(N), BK=64; 16 stages (one per k-chunk).
// Stage = Ahi 16KB + Alo 16KB + B 16KB = 48KB; 2-stage pipeline = 96KB smem
// -> 2 CTAs/SM (256 threads, ~110 regs) so barrier stalls overlap.
// 8 warps, warp tile 32x64 (2 m-frags x 8 n-frags), 64 acc regs.
// ---------------------------------------------------------------------------
#define G_STAGE_BYTES 49152
#define G_SMEM_TOTAL  (2 * G_STAGE_BYTES)   // 98304

__device__ __forceinline__ void gemm_copy_stage(
    uint32_t sbuf, int kc, int mt, int nt, int tid,
    const uint8_t* Ahi, const uint8_t* Alo, const uint8_t* Bhi)
{
    const uint8_t* AhiSrc = Ahi + ((size_t)(mt * 16 + kc)) * 16384;
    const uint8_t* AloSrc = Alo + ((size_t)(mt * 16 + kc)) * 16384;
    const uint8_t* BSrc   = Bhi + ((size_t)(kc * 16 + nt)) * 16384;
#pragma unroll
    for (int i = 0; i < 4; ++i) {
        const int ch = tid + i * 256;
        cp_async16(sbuf + ch * 16,          AhiSrc + (size_t)ch * 16);
        cp_async16(sbuf + 16384 + ch * 16,  AloSrc + (size_t)ch * 16);
        cp_async16(sbuf + 32768 + ch * 16,  BSrc   + (size_t)ch * 16);
    }
    cp_commit();
}

__global__ __launch_bounds__(256, 2)
void gemm_bf16x2f_mma_kernel(const uint8_t* __restrict__ Ahi, const uint8_t* __restrict__ Alo,
                             const uint8_t* __restrict__ Bhi,
                             float* __restrict__ C)
{
    extern __shared__ char smem[];
    const uint32_t sb = smem_to_u32(smem);
    const int tid = threadIdx.x;
    const int wid = tid >> 5;
    const int lane = tid & 31;
    const int nt = blockIdx.x;   // 0..15  (N tile of 128)  -- fastest: A reuse in L2
    const int mt = blockIdx.y;   // 0..255 (M tile of 128)

    const int wm = (wid >> 1) * 32;   // warp m offset (0..96)
    const int wn = (wid & 1) * 64;    // warp n offset (0 or 64)

    float acc[2][8][4];
#pragma unroll
    for (int i = 0; i < 2; ++i)
#pragma unroll
        for (int j = 0; j < 8; ++j)
#pragma unroll
            for (int r = 0; r < 4; ++r) acc[i][j][r] = 0.f;

    gemm_copy_stage(sb + 0 * G_STAGE_BYTES, 0, mt, nt, tid, Ahi, Alo, Bhi);
    gemm_copy_stage(sb + 1 * G_STAGE_BYTES, 1, mt, nt, tid, Ahi, Alo, Bhi);

    const int lrow15 = lane & 15;
    const int lhalf  = lane >> 4;

    for (int it = 0; it < 16; ++it) {
        if (it < 15) cp_wait<1>();
        else         cp_wait<0>();
        __syncthreads();

        const uint32_t stBase = sb + (uint32_t)(it & 1) * G_STAGE_BYTES;
        const uint32_t hiBase = stBase;
        const uint32_t loBase = stBase + 16384;
        const uint32_t bBase  = stBase + 32768;

#pragma unroll
        for (int kk = 0; kk < 4; ++kk) {
            const int unit = 2 * kk + lhalf;
            uint32_t ah[2][4], al[2][4];
            uint32_t b[8][2];
#pragma unroll
            for (int mi = 0; mi < 2; ++mi) {
                const int row = wm + mi * 16 + lrow15;
                const uint32_t sw = ((unit ^ (row & 7)) << 4);
                ldmatrix_x4(ah[mi][0], ah[mi][1], ah[mi][2], ah[mi][3],
                            hiBase + row * 128 + sw);
                ldmatrix_x4(al[mi][0], al[mi][1], al[mi][2], al[mi][3],
                            loBase + row * 128 + sw);
            }
#pragma unroll
            for (int j = 0; j < 4; ++j) {
                const int row = wn + j * 16 + lrow15;
                const uint32_t addr = bBase + row * 128 + ((unit ^ (row & 7)) << 4);
                uint32_t r0, r1, r2, r3;
                ldmatrix_x4(r0, r1, r2, r3, addr);
                b[2*j][0]   = r0; b[2*j][1]   = r2;
                b[2*j+1][0] = r1; b[2*j+1][1] = r3;
            }
#pragma unroll
            for (int mi = 0; mi < 2; ++mi)
#pragma unroll
                for (int ni = 0; ni < 8; ++ni) {
                    mma_bf16(acc[mi][ni], ah[mi], b[ni]);
                    mma_bf16(acc[mi][ni], al[mi], b[ni]);
                }
        }

        __syncthreads();
        if (it + 2 < 16)
            gemm_copy_stage(sb + (uint32_t)(it & 1) * G_STAGE_BYTES,
                            it + 2, mt, nt, tid, Ahi, Alo, Bhi);
    }

    const int rbase = mt * 128 + wm + (lane >> 2);
    const int cbase = nt * 128 + wn + 2 * (lane & 3);
#pragma unroll
    for (int mi = 0; mi < 2; ++mi) {
#pragma unroll
        for (int ni = 0; ni < 8; ++ni) {
            const int r0 = rbase + mi * 16;
            const int c0 = cbase + ni * 8;
            float2* p0 = (float2*)(C + (size_t)r0 * K_CODE + c0);
            float2* p1 = (float2*)(C + (size_t)(r0 + 8) * K_CODE + c0);
            *p0 = make_float2(acc[mi][ni][0], acc[mi][ni][1]);
            *p1 = make_float2(acc[mi][ni][2], acc[mi][ni][3]);
        }
    }
}

// ---------------------------------------------------------------------------
// fast 2^y (degree-6 poly after round-to-nearest split); avoids MUFU cliff.
// ---------------------------------------------------------------------------
__device__ __forceinline__ float fast_exp2(float y)
{
    float r = rintf(y);
    float f = y - r;
    float p = 1.5403530e-4f;
    p = fmaf(p, f, 1.3333558e-3f);
    p = fmaf(p, f, 9.6181291e-3f);
    p = fmaf(p, f, 5.5504109e-2f);
    p = fmaf(p, f, 2.4022651e-1f);
    p = fmaf(p, f, 6.9314718e-1f);
    p = fmaf(p, f, 1.0f);
    int ei = (int)r;
    if (ei < -126) return 0.f;
    float s = __int_as_float((ei + 127) << 23);
    return p * s;
}

// ---------------------------------------------------------------------------
// Kernel 2: row pass, warp-per-token (no block syncs).
// 512 CTAs x 8 warps, 8 tokens/warp. Lane holds 64 logits in registers;
// warp-shuffle reductions; per-warp diversity partials written coalesced.
// Candidate threshold 0.4 (covers the 2-split GEMM logit error).
// ---------------------------------------------------------------------------
__global__ __launch_bounds__(256)
void row_pass_kernel(const float* __restrict__ S)
{
    const int lane = threadIdx.x & 31;
    const int warp = threadIdx.x >> 5;
    const int gw = blockIdx.x * 8 + warp;        // global warp id, 0..4095

    float dreg[64];
#pragma unroll
    for (int j = 0; j < 64; ++j) dreg[j] = 0.f;
    float hsum = 0.f;

    for (int t = 0; t < 8; ++t) {
        const int tok = gw * 8 + t;
        const float4* row4 = (const float4*)(S + (size_t)tok * K_CODE);

        float v[64];
#pragma unroll
        for (int jj = 0; jj < 16; ++jj) {
            float4 x = row4[lane + 32 * jj];
            v[4*jj+0] = x.x; v[4*jj+1] = x.y; v[4*jj+2] = x.z; v[4*jj+3] = x.w;
        }

        // ---- max (warp) ----
        float m = v[0];
#pragma unroll
        for (int j = 1; j < 64; ++j) m = fmaxf(m, v[j]);
#pragma unroll
        for (int off = 16; off > 0; off >>= 1)
            m = fmaxf(m, __shfl_xor_sync(0xffffffffu, m, off));

        // ---- candidates within 0.4 of max ----
        const float thr = m - 0.4f;
        int cnt_l = 0;
#pragma unroll
        for (int j = 0; j < 64; ++j) cnt_l += (v[j] >= thr) ? 1 : 0;
        int pre = cnt_l;
#pragma unroll
        for (int off = 1; off < 32; off <<= 1) {
            int n = __shfl_up_sync(0xffffffffu, pre, off);
            if (lane >= off) pre += n;
        }
        const int total = __shfl_sync(0xffffffffu, pre, 31);
        int slot = pre - cnt_l;   // exclusive prefix
        if (cnt_l) {
#pragma unroll
            for (int j = 0; j < 64; ++j) {
                if (v[j] >= thr) {
                    if (slot < NCAND)
                        g_cand_idx[tok][slot] = 4 * lane + 128 * (j >> 2) + (j & 3);
                    ++slot;
                }
            }
        }
        if (lane == 0) g_cand_cnt[tok] = (total < NCAND) ? total : NCAND;

        // ---- softmax stats ----
        const float LOG2E = 1.4426950408889634f;
        float s0 = 0.f, s1 = 0.f;
#pragma unroll
        for (int j = 0; j < 64; ++j) {
            float y = (v[j] - m) * LOG2E;
            float e = fast_exp2(y);
            v[j] = e;
            s0 += e;
            s1 = fmaf(e, y, s1);
        }
#pragma unroll
        for (int off = 16; off > 0; off >>= 1) {
            s0 += __shfl_xor_sync(0xffffffffu, s0, off);
            s1 += __shfl_xor_sync(0xffffffffu, s1, off);
        }
        const float inv = 1.f / s0;
#pragma unroll
        for (int j = 0; j < 64; ++j) dreg[j] = fmaf(v[j], inv, dreg[j]);
        hsum += s1 * inv - log2f(s0);
    }

    // per-warp diversity partial (coalesced float4 stores)
    float4* dp = (float4*)(g_div_part + (size_t)gw * K_CODE);
#pragma unroll
    for (int jj = 0; jj < 16; ++jj)
        dp[lane + 32 * jj] = make_float4(dreg[4*jj], dreg[4*jj+1], dreg[4*jj+2], dreg[4*jj+3]);
    if (lane == 0) g_h_part[gw] = hsum;
}

// ---------------------------------------------------------------------------
// Kernel 2b: fp64 refinement of argmax among candidates (1 warp/token).
// ---------------------------------------------------------------------------
__global__ __launch_bounds__(256)
void refine_kernel(const float* __restrict__ inputs,
                   const float* __restrict__ codebook,
                   float* __restrict__ nn_out)
{
    const int warp = threadIdx.x >> 5;
    const int lane = threadIdx.x & 31;
    const int tok = blockIdx.x * 8 + warp;

    const int cnt = g_cand_cnt[tok];
    int best = g_cand_idx[tok][0];

    if (cnt > 1) {
        const float* xr = inputs + (size_t)tok * D_DIM;
        double bv = -1e300;
        int bi = INT_MAX;
        for (int c = 0; c < cnt; ++c) {
            const int idx = g_cand_idx[tok][c];
            const float* cr = codebook + (size_t)idx * D_DIM;
            double s = 0.0;
            for (int i = lane; i < D_DIM; i += 32)
                s += (double)xr[i] * (double)cr[i];
#pragma unroll
            for (int off = 16; off > 0; off >>= 1)
                s += __shfl_down_sync(0xffffffffu, s, off);
            s = __shfl_sync(0xffffffffu, s, 0);
            if (s > bv || (s == bv && idx < bi)) { bv = s; bi = idx; }
        }
        best = bi;
    }

    if (lane == 0) {
        g_nn[tok] = best;
        nn_out[tok] = (float)best;
    }
}

// ---------------------------------------------------------------------------
// Kernel 3a: diversity reduce across the 4096 per-warp partials (16 CTAs).
// ---------------------------------------------------------------------------
__global__ __launch_bounds__(128)
void div_reduce_kernel()
{
    const int col = blockIdx.x * 128 + threadIdx.x;
    float s = 0.f;
#pragma unroll 8
    for (int w = 0; w < RP_WARPS; ++w)
        s += g_div_part[(size_t)w * K_CODE + col];
    float dv = s * (1.f / (float)M_TOK);
    float acc = dv * log2f(dv + 1e-8f);

    __shared__ float sa[128];
    sa[threadIdx.x] = acc;
    __syncthreads();
    for (int off = 64; off > 0; off >>= 1) {
        if (threadIdx.x < off) sa[threadIdx.x] += sa[threadIdx.x + off];
        __syncthreads();
    }
    if (threadIdx.x == 0) g_acc_part[blockIdx.x] = sa[0];
}

// ---------------------------------------------------------------------------
// Kernel 3b: final scalar loss.
// ---------------------------------------------------------------------------
__global__ __launch_bounds__(256)
void finalize2_kernel()
{
    const int tid = threadIdx.x;
    float h = 0.f;
#pragma unroll
    for (int i = 0; i < RP_WARPS / 256; ++i)     // 16 per thread
        h += g_h_part[tid * (RP_WARPS / 256) + i];
    float a = (tid < 16) ? g_acc_part[tid] : 0.f;

    __shared__ float sh[256], sa[256];
    sh[tid] = h; sa[tid] = a;
    __syncthreads();
    for (int off = 128; off > 0; off >>= 1) {
        if (tid < off) { sh[tid] += sh[tid + off]; sa[tid] += sa[tid + off]; }
        __syncthreads();
    }
    if (tid == 0) {
        float h_clust = -sh[0] / (float)M_TOK;
        g_loss[0] = h_clust + sa[0];   // loss = h_clust - (-sa) = h_clust + sa
    }
}

// ---------------------------------------------------------------------------
// Kernel 4: broadcast scalar loss into the qloss region.
// ---------------------------------------------------------------------------
__global__ __launch_bounds__(256)
void fill_loss_kernel(float* __restrict__ dst)
{
    const float v = g_loss[0];
    const float4 v4 = make_float4(v, v, v, v);
    size_t i = ((size_t)blockIdx.x * blockDim.x + threadIdx.x);
    const size_t stride = (size_t)gridDim.x * blockDim.x;
    const size_t n4 = LOSS_N / 4;
    float4* d4 = (float4*)dst;
    for (; i < n4; i += stride) d4[i] = v4;
}

// ---------------------------------------------------------------------------
// Kernel 5: copy codebook into output.
// ---------------------------------------------------------------------------
__global__ __launch_bounds__(256)
void copy_cb_kernel(const float* __restrict__ src, float* __restrict__ dst)
{
    size_t i = ((size_t)blockIdx.x * blockDim.x + threadIdx.x);
    const size_t stride = (size_t)gridDim.x * blockDim.x;
    const size_t n4 = CB_N / 4;
    const float4* s4 = (const float4*)src;
    float4* d4 = (float4*)dst;
    for (; i < n4; i += stride) d4[i] = s4[i];
}

// ---------------------------------------------------------------------------
// Kernel 6: gather + center + L2-normalize + straight-through identity.
// ---------------------------------------------------------------------------
__global__ __launch_bounds__(256)
void quantize_kernel(const float* __restrict__ inputs,
                     const float* __restrict__ codebook,
                     float* __restrict__ qout)
{
    const int warp = threadIdx.x >> 5;
    const int lane = threadIdx.x & 31;
    const int tok = blockIdx.x * 8 + warp;
    const int idx = g_nn[tok];
    const float* row = codebook + (size_t)idx * D_DIM;

    float4 x[8];
    float sum = 0.f;
#pragma unroll
    for (int c = 0; c < 8; ++c) {
        x[c] = *(const float4*)(row + c * 128 + lane * 4);
        sum += x[c].x + x[c].y + x[c].z + x[c].w;
    }
#pragma unroll
    for (int off = 16; off > 0; off >>= 1)
        sum += __shfl_xor_sync(0xffffffffu, sum, off);
    const float mean = sum * (1.f / (float)D_DIM);

    float ss = 0.f;
#pragma unroll
    for (int c = 0; c < 8; ++c) {
        x[c].x -= mean; x[c].y -= mean; x[c].z -= mean; x[c].w -= mean;
        ss += x[c].x * x[c].x + x[c].y * x[c].y + x[c].z * x[c].z + x[c].w * x[c].w;
    }
#pragma unroll
    for (int off = 16; off > 0; off >>= 1)
        ss += __shfl_xor_sync(0xffffffffu, ss, off);
    const float invn = 1.f / sqrtf(ss);

    const float* xin = inputs + (size_t)tok * D_DIM;
    float* out = qout + (size_t)tok * D_DIM;
#pragma unroll
    for (int c = 0; c < 8; ++c) {
        float4 iv = *(const float4*)(xin + c * 128 + lane * 4);
        float4 v;
        v.x = iv.x + (x[c].x * invn - iv.x);
        v.y = iv.y + (x[c].y * invn - iv.y);
        v.z = iv.z + (x[c].z * invn - iv.z);
        v.w = iv.w + (x[c].w * invn - iv.w);
        *(float4*)(out + c * 128 + lane * 4) = v;
    }
}

// ---------------------------------------------------------------------------
extern "C" void kernel_launch(void* const* d_in, const int* in_sizes, int n_in,
                              void* d_out, int out_size)
{
    const float* inputs   = (const float*)d_in[0];
    const float* codebook = (const float*)d_in[1];
    float* out = (float*)d_out;

    float *logits;
    uint4 *Ahi, *Alo, *Bhi, *Blo;
    cudaGetSymbolAddress((void**)&logits, g_logits);
    cudaGetSymbolAddress((void**)&Ahi, g_Ahi);
    cudaGetSymbolAddress((void**)&Alo, g_Alo);
    cudaGetSymbolAddress((void**)&Bhi, g_Bhi);
    cudaGetSymbolAddress((void**)&Blo, g_Blo);

    // 0) split fp32 -> bf16 hi/lo, pre-tiled + swizzled
    split_kernel<<<(M_TOK * 128) / 256, 256>>>(inputs, Ahi, Alo, M_TOK * 128, 16, 1);
    split_kernel<<<(K_CODE * 128) / 256, 256>>>(codebook, Bhi, Blo, K_CODE * 128, 1, 16);

    // 1) bf16 2-split (hi/lo fused) similarity GEMM, tile 128x128, 2 CTA/SM
    cudaFuncSetAttribute(gemm_bf16x2f_mma_kernel,
                         cudaFuncAttributeMaxDynamicSharedMemorySize, G_SMEM_TOTAL);
    {
        dim3 grid(K_CODE / 128, M_TOK / 128);   // (16, 256), nt fastest
        gemm_bf16x2f_mma_kernel<<<grid, 256, G_SMEM_TOTAL>>>(
            (const uint8_t*)Ahi, (const uint8_t*)Alo, (const uint8_t*)Bhi, logits);
    }

    // 2) row pass (warp-per-token)
    row_pass_kernel<<<RP_WARPS / 8, 256>>>(logits);
    // 2b) fp64 refine of near-tied argmax -> final nn_idx
    refine_kernel<<<M_TOK / 8, 256>>>(inputs, codebook, out + NN_OFF);
    // 3) loss reduction
    div_reduce_kernel<<<16, 128>>>();
    finalize2_kernel<<<1, 256>>>();
    // 4) broadcast loss
    fill_loss_kernel<<<8192, 256>>>(out + LOSS_OFF);
    // 5) codebook passthrough
    copy_cb_kernel<<<2048, 256>>>(codebook, out + CB_OFF);
    // 6) quantized rows
    quantize_kernel<<<M_TOK / 8, 256>>>(inputs, codebook, out + QUANT_OFF);
}

// round 14
// speedup vs baseline: 3.3809x; 1.2370x over previous
#include <cuda_runtime.h>
#include <cuda_bf16.h>
#include <cstdint>
#include <cstddef>
#include <climits>

// ---------------------------------------------------------------------------
// Problem shape (fixed by the dataset)
//   inputs:   [16, 2048, 1024] f32  -> M = 32768 tokens, D = 1024
//   codebook: [2048, 1024]     f32  -> K = 2048 codes
// Outputs concatenated (f32):
//   quantized  [32768,1024]  @ 0
//   qloss      [32768,2048]  @ 33554432   (scalar broadcast)
//   nn_idx     [32768]       @ 100663296  (as float)
//   codebook   [2048,1024]   @ 100696064
// ---------------------------------------------------------------------------
#define M_TOK   32768
#define K_CODE  2048
#define D_DIM   1024

#define QUANT_OFF 0
#define LOSS_OFF  33554432
#define NN_OFF    100663296
#define CB_OFF    100696064
#define LOSS_N    67108864
#define CB_N      2097152

#define NCAND 16

// ------------------------- scratch (device globals) ------------------------
__device__ float g_logits[(size_t)M_TOK * K_CODE];   // 256 MiB

#define RP_WARPS 4096          // 512 CTAs x 8 warps, 8 tokens per warp
__device__ float g_div_part[(size_t)RP_WARPS * K_CODE];   // 32 MiB per-warp partials
__device__ float g_h_part[RP_WARPS];
__device__ float g_acc_part[16];
__device__ int   g_nn[M_TOK];
__device__ float g_loss[1];
__device__ int   g_cand_cnt[M_TOK];
__device__ int   g_cand_idx[M_TOK][NCAND];

// bf16 hi operands, pre-tiled + pre-SW128-swizzled into 16KB blocks of
// [128 rows x 64 cols bf16] (= 128 rows x 128B).
//   A blocks ordered [m_tile (256)][k_chunk (16)]
//   B blocks ordered [k_chunk (16)][n_block (16)]
__device__ uint4 g_Ahi[(size_t)M_TOK * D_DIM / 8];   // 64 MiB
__device__ uint4 g_Bhi[(size_t)K_CODE * D_DIM / 8];  // 4 MiB

// ------------------------- PTX helpers ---------------------------
__device__ __forceinline__ uint32_t smem_to_u32(const void* p) {
    uint32_t a;
    asm("{ .reg .u64 t; cvta.to.shared.u64 t, %1; cvt.u32.u64 %0, t; }" : "=r"(a) : "l"(p));
    return a;
}

__device__ __forceinline__ void cp_async16(uint32_t dst, const void* src) {
    asm volatile("cp.async.cg.shared.global [%0], [%1], 16;" :: "r"(dst), "l"(src) : "memory");
}
__device__ __forceinline__ void cp_commit() {
    asm volatile("cp.async.commit_group;" ::: "memory");
}
template <int N>
__device__ __forceinline__ void cp_wait() {
    asm volatile("cp.async.wait_group %0;" :: "n"(N) : "memory");
}

__device__ __forceinline__ void ldmatrix_x4(uint32_t& r0, uint32_t& r1,
                                            uint32_t& r2, uint32_t& r3, uint32_t addr) {
    asm volatile("ldmatrix.sync.aligned.m8n8.x4.shared.b16 {%0,%1,%2,%3}, [%4];"
                 : "=r"(r0), "=r"(r1), "=r"(r2), "=r"(r3) : "r"(addr));
}

__device__ __forceinline__ void mma_bf16(float* c, const uint32_t* a, const uint32_t* b) {
    asm volatile(
        "mma.sync.aligned.m16n8k16.row.col.f32.bf16.bf16.f32 "
        "{%0,%1,%2,%3}, {%4,%5,%6,%7}, {%8,%9}, {%0,%1,%2,%3};"
        : "+f"(c[0]), "+f"(c[1]), "+f"(c[2]), "+f"(c[3])
        : "r"(a[0]), "r"(a[1]), "r"(a[2]), "r"(a[3]), "r"(b[0]), "r"(b[1]));
}

// ---------------------------------------------------------------------------
// Kernel 0: fp32 -> bf16 (hi only), tiled into 16KB SW128-swizzled blocks.
// One thread = 8 consecutive columns (16B of bf16 output).
// blk = tile*tileStride + kc*kcStride   (A: 16,1   B: 1,16)
// ---------------------------------------------------------------------------
__global__ __launch_bounds__(256)
void split_kernel(const float* __restrict__ src,
                  uint4* __restrict__ hi,
                  int nchunks, int tileStride, int kcStride)
{
    int i = blockIdx.x * blockDim.x + threadIdx.x;
    if (i >= nchunks) return;
    const int c8   = i & 127;
    const int row  = i >> 7;
    const int kc   = c8 >> 3;
    const int g    = c8 & 7;
    const int tile = row >> 7;
    const int r    = row & 127;

    const size_t blk = (size_t)tile * tileStride + (size_t)kc * kcStride;
    uint32_t off = r * 128 + g * 16;
    off ^= (off >> 3) & 0x70;                     // SW128 swizzle
    const size_t dst = blk * 1024 + (off >> 4);

    const float4* s4 = (const float4*)(src + ((size_t)row << 10) + (c8 << 3));
    float4 x0 = s4[0], x1 = s4[1];
    float xs[8] = {x0.x, x0.y, x0.z, x0.w, x1.x, x1.y, x1.z, x1.w};
    uint32_t hw[4];
#pragma unroll
    for (int j = 0; j < 4; ++j) {
        __nv_bfloat16 h0 = __float2bfloat16_rn(xs[2*j]);
        __nv_bfloat16 h1 = __float2bfloat16_rn(xs[2*j+1]);
        hw[j] = (uint32_t)__bfloat16_as_ushort(h0) | ((uint32_t)__bfloat16_as_ushort(h1) << 16);
    }
    hi[dst] = make_uint4(hw[0], hw[1], hw[2], hw[3]);
}

// ---------------------------------------------------------------------------
// Kernel 1: single-split bf16 GEMM via mma.sync:  C ~= Ahi * Bhi^T.
// (Logit abs error sigma ~0.09; argmax protected by the 1.25 candidate
//  window + fp64 refine; loss bias ~7e-5 rel, well under the 1e-3 gate.)
// CTA tile 128(M) x 128(N), BK=64; 16 stages (one per k-chunk).
// Stage = A 16KB + B 16KB = 32KB; 3-stage pipeline = 96KB; 2 CTAs/SM.
// 8 warps, warp tile 32x64 (2 m-frags x 8 n-frags), 64 acc regs.
// ---------------------------------------------------------------------------
#define G_STAGE_BYTES 32768
#define G_SMEM_TOTAL  (3 * G_STAGE_BYTES)   // 98304

__device__ __forceinline__ void gemm_copy_stage(
    uint32_t sbuf, int kc, int mt, int nt, int tid,
    const uint8_t* Ahi, const uint8_t* Bhi)
{
    const uint8_t* ASrc = Ahi + ((size_t)(mt * 16 + kc)) * 16384;
    const uint8_t* BSrc = Bhi + ((size_t)(kc * 16 + nt)) * 16384;
#pragma unroll
    for (int i = 0; i < 4; ++i) {
        const int ch = tid + i * 256;
        cp_async16(sbuf + ch * 16,          ASrc + (size_t)ch * 16);
        cp_async16(sbuf + 16384 + ch * 16,  BSrc + (size_t)ch * 16);
    }
    cp_commit();
}

__global__ __launch_bounds__(256, 2)
void gemm_bf16x1_mma_kernel(const uint8_t* __restrict__ Ahi,
                            const uint8_t* __restrict__ Bhi,
                            float* __restrict__ C)
{
    extern __shared__ char smem[];
    const uint32_t sb = smem_to_u32(smem);
    const int tid = threadIdx.x;
    const int wid = tid >> 5;
    const int lane = tid & 31;
    const int nt = blockIdx.x;   // 0..15  (N tile of 128)  -- fastest: A reuse in L2
    const int mt = blockIdx.y;   // 0..255 (M tile of 128)

    const int wm = (wid >> 1) * 32;   // warp m offset (0..96)
    const int wn = (wid & 1) * 64;    // warp n offset (0 or 64)

    float acc[2][8][4];
#pragma unroll
    for (int i = 0; i < 2; ++i)
#pragma unroll
        for (int j = 0; j < 8; ++j)
#pragma unroll
            for (int r = 0; r < 4; ++r) acc[i][j][r] = 0.f;

    gemm_copy_stage(sb + 0 * G_STAGE_BYTES, 0, mt, nt, tid, Ahi, Bhi);
    gemm_copy_stage(sb + 1 * G_STAGE_BYTES, 1, mt, nt, tid, Ahi, Bhi);
    gemm_copy_stage(sb + 2 * G_STAGE_BYTES, 2, mt, nt, tid, Ahi, Bhi);

    const int lrow15 = lane & 15;
    const int lhalf  = lane >> 4;

    for (int it = 0; it < 16; ++it) {
        if (it < 14)       cp_wait<2>();
        else if (it == 14) cp_wait<1>();
        else               cp_wait<0>();
        __syncthreads();

        const uint32_t aBase = sb + (uint32_t)(it % 3) * G_STAGE_BYTES;
        const uint32_t bBase = aBase + 16384;

#pragma unroll
        for (int kk = 0; kk < 4; ++kk) {
            const int unit = 2 * kk + lhalf;
            uint32_t a[2][4];
            uint32_t b[8][2];
#pragma unroll
            for (int mi = 0; mi < 2; ++mi) {
                const int row = wm + mi * 16 + lrow15;
                ldmatrix_x4(a[mi][0], a[mi][1], a[mi][2], a[mi][3],
                            aBase + row * 128 + ((unit ^ (row & 7)) << 4));
            }
#pragma unroll
            for (int j = 0; j < 4; ++j) {
                const int row = wn + j * 16 + lrow15;
                uint32_t r0, r1, r2, r3;
                ldmatrix_x4(r0, r1, r2, r3,
                            bBase + row * 128 + ((unit ^ (row & 7)) << 4));
                b[2*j][0]   = r0; b[2*j][1]   = r2;
                b[2*j+1][0] = r1; b[2*j+1][1] = r3;
            }
#pragma unroll
            for (int mi = 0; mi < 2; ++mi)
#pragma unroll
                for (int ni = 0; ni < 8; ++ni)
                    mma_bf16(acc[mi][ni], a[mi], b[ni]);
        }

        __syncthreads();
        if (it + 3 < 16)
            gemm_copy_stage(sb + (uint32_t)((it + 3) % 3) * G_STAGE_BYTES,
                            it + 3, mt, nt, tid, Ahi, Bhi);
    }

    const int rbase = mt * 128 + wm + (lane >> 2);
    const int cbase = nt * 128 + wn + 2 * (lane & 3);
#pragma unroll
    for (int mi = 0; mi < 2; ++mi) {
#pragma unroll
        for (int ni = 0; ni < 8; ++ni) {
            const int r0 = rbase + mi * 16;
            const int c0 = cbase + ni * 8;
            float2* p0 = (float2*)(C + (size_t)r0 * K_CODE + c0);
            float2* p1 = (float2*)(C + (size_t)(r0 + 8) * K_CODE + c0);
            *p0 = make_float2(acc[mi][ni][0], acc[mi][ni][1]);
            *p1 = make_float2(acc[mi][ni][2], acc[mi][ni][3]);
        }
    }
}

// ---------------------------------------------------------------------------
// fast 2^y (degree-6 poly after round-to-nearest split); avoids MUFU cliff.
// ---------------------------------------------------------------------------
__device__ __forceinline__ float fast_exp2(float y)
{
    float r = rintf(y);
    float f = y - r;
    float p = 1.5403530e-4f;
    p = fmaf(p, f, 1.3333558e-3f);
    p = fmaf(p, f, 9.6181291e-3f);
    p = fmaf(p, f, 5.5504109e-2f);
    p = fmaf(p, f, 2.4022651e-1f);
    p = fmaf(p, f, 6.9314718e-1f);
    p = fmaf(p, f, 1.0f);
    int ei = (int)r;
    if (ei < -126) return 0.f;
    float s = __int_as_float((ei + 127) << 23);
    return p * s;
}

// ---------------------------------------------------------------------------
// Kernel 2: row pass, warp-per-token (no block syncs).
// 512 CTAs x 8 warps, 8 tokens/warp. Lane holds 64 logits in registers;
// warp-shuffle reductions; per-warp diversity partials written coalesced.
// Candidate threshold 1.25 (covers the single-split GEMM logit error).
// ---------------------------------------------------------------------------
__global__ __launch_bounds__(256)
void row_pass_kernel(const float* __restrict__ S)
{
    const int lane = threadIdx.x & 31;
    const int warp = threadIdx.x >> 5;
    const int gw = blockIdx.x * 8 + warp;        // global warp id, 0..4095

    float dreg[64];
#pragma unroll
    for (int j = 0; j < 64; ++j) dreg[j] = 0.f;
    float hsum = 0.f;

    for (int t = 0; t < 8; ++t) {
        const int tok = gw * 8 + t;
        const float4* row4 = (const float4*)(S + (size_t)tok * K_CODE);

        float v[64];
#pragma unroll
        for (int jj = 0; jj < 16; ++jj) {
            float4 x = row4[lane + 32 * jj];
            v[4*jj+0] = x.x; v[4*jj+1] = x.y; v[4*jj+2] = x.z; v[4*jj+3] = x.w;
        }

        // ---- max (warp) ----
        float m = v[0];
#pragma unroll
        for (int j = 1; j < 64; ++j) m = fmaxf(m, v[j]);
#pragma unroll
        for (int off = 16; off > 0; off >>= 1)
            m = fmaxf(m, __shfl_xor_sync(0xffffffffu, m, off));

        // ---- candidates within 1.25 of max ----
        const float thr = m - 1.25f;
        int cnt_l = 0;
#pragma unroll
        for (int j = 0; j < 64; ++j) cnt_l += (v[j] >= thr) ? 1 : 0;
        int pre = cnt_l;
#pragma unroll
        for (int off = 1; off < 32; off <<= 1) {
            int n = __shfl_up_sync(0xffffffffu, pre, off);
            if (lane >= off) pre += n;
        }
        const int total = __shfl_sync(0xffffffffu, pre, 31);
        int slot = pre - cnt_l;   // exclusive prefix
        if (cnt_l) {
#pragma unroll
            for (int j = 0; j < 64; ++j) {
                if (v[j] >= thr) {
                    if (slot < NCAND)
                        g_cand_idx[tok][slot] = 4 * lane + 128 * (j >> 2) + (j & 3);
                    ++slot;
                }
            }
        }
        if (lane == 0) g_cand_cnt[tok] = (total < NCAND) ? total : NCAND;

        // ---- softmax stats ----
        const float LOG2E = 1.4426950408889634f;
        float s0 = 0.f, s1 = 0.f;
#pragma unroll
        for (int j = 0; j < 64; ++j) {
            float y = (v[j] - m) * LOG2E;
            float e = fast_exp2(y);
            v[j] = e;
            s0 += e;
            s1 = fmaf(e, y, s1);
        }
#pragma unroll
        for (int off = 16; off > 0; off >>= 1) {
            s0 += __shfl_xor_sync(0xffffffffu, s0, off);
            s1 += __shfl_xor_sync(0xffffffffu, s1, off);
        }
        const float inv = 1.f / s0;
#pragma unroll
        for (int j = 0; j < 64; ++j) dreg[j] = fmaf(v[j], inv, dreg[j]);
        hsum += s1 * inv - log2f(s0);
    }

    // per-warp diversity partial (coalesced float4 stores)
    float4* dp = (float4*)(g_div_part + (size_t)gw * K_CODE);
#pragma unroll
    for (int jj = 0; jj < 16; ++jj)
        dp[lane + 32 * jj] = make_float4(dreg[4*jj], dreg[4*jj+1], dreg[4*jj+2], dreg[4*jj+3]);
    if (lane == 0) g_h_part[gw] = hsum;
}

// ---------------------------------------------------------------------------
// Kernel 2b: fp64 refinement of argmax among candidates (1 warp/token).
// ---------------------------------------------------------------------------
__global__ __launch_bounds__(256)
void refine_kernel(const float* __restrict__ inputs,
                   const float* __restrict__ codebook,
                   float* __restrict__ nn_out)
{
    const int warp = threadIdx.x >> 5;
    const int lane = threadIdx.x & 31;
    const int tok = blockIdx.x * 8 + warp;

    const int cnt = g_cand_cnt[tok];
    int best = g_cand_idx[tok][0];

    if (cnt > 1) {
        const float* xr = inputs + (size_t)tok * D_DIM;
        double bv = -1e300;
        int bi = INT_MAX;
        for (int c = 0; c < cnt; ++c) {
            const int idx = g_cand_idx[tok][c];
            const float* cr = codebook + (size_t)idx * D_DIM;
            double s = 0.0;
            for (int i = lane; i < D_DIM; i += 32)
                s += (double)xr[i] * (double)cr[i];
#pragma unroll
            for (int off = 16; off > 0; off >>= 1)
                s += __shfl_down_sync(0xffffffffu, s, off);
            s = __shfl_sync(0xffffffffu, s, 0);
            if (s > bv || (s == bv && idx < bi)) { bv = s; bi = idx; }
        }
        best = bi;
    }

    if (lane == 0) {
        g_nn[tok] = best;
        nn_out[tok] = (float)best;
    }
}

// ---------------------------------------------------------------------------
// Kernel 3a: diversity reduce across the 4096 per-warp partials (16 CTAs).
// ---------------------------------------------------------------------------
__global__ __launch_bounds__(128)
void div_reduce_kernel()
{
    const int col = blockIdx.x * 128 + threadIdx.x;
    float s = 0.f;
#pragma unroll 8
    for (int w = 0; w < RP_WARPS; ++w)
        s += g_div_part[(size_t)w * K_CODE + col];
    float dv = s * (1.f / (float)M_TOK);
    float acc = dv * log2f(dv + 1e-8f);

    __shared__ float sa[128];
    sa[threadIdx.x] = acc;
    __syncthreads();
    for (int off = 64; off > 0; off >>= 1) {
        if (threadIdx.x < off) sa[threadIdx.x] += sa[threadIdx.x + off];
        __syncthreads();
    }
    if (threadIdx.x == 0) g_acc_part[blockIdx.x] = sa[0];
}

// ---------------------------------------------------------------------------
// Kernel 3b: final scalar loss.
// ---------------------------------------------------------------------------
__global__ __launch_bounds__(256)
void finalize2_kernel()
{
    const int tid = threadIdx.x;
    float h = 0.f;
#pragma unroll
    for (int i = 0; i < RP_WARPS / 256; ++i)     // 16 per thread
        h += g_h_part[tid * (RP_WARPS / 256) + i];
    float a = (tid < 16) ? g_acc_part[tid] : 0.f;

    __shared__ float sh[256], sa[256];
    sh[tid] = h; sa[tid] = a;
    __syncthreads();
    for (int off = 128; off > 0; off >>= 1) {
        if (tid < off) { sh[tid] += sh[tid + off]; sa[tid] += sa[tid + off]; }
        __syncthreads();
    }
    if (tid == 0) {
        float h_clust = -sh[0] / (float)M_TOK;
        g_loss[0] = h_clust + sa[0];   // loss = h_clust - (-sa) = h_clust + sa
    }
}

// ---------------------------------------------------------------------------
// Kernel 4: broadcast scalar loss into the qloss region.
// ---------------------------------------------------------------------------
__global__ __launch_bounds__(256)
void fill_loss_kernel(float* __restrict__ dst)
{
    const float v = g_loss[0];
    const float4 v4 = make_float4(v, v, v, v);
    size_t i = ((size_t)blockIdx.x * blockDim.x + threadIdx.x);
    const size_t stride = (size_t)gridDim.x * blockDim.x;
    const size_t n4 = LOSS_N / 4;
    float4* d4 = (float4*)dst;
    for (; i < n4; i += stride) d4[i] = v4;
}

// ---------------------------------------------------------------------------
// Kernel 5: copy codebook into output.
// ---------------------------------------------------------------------------
__global__ __launch_bounds__(256)
void copy_cb_kernel(const float* __restrict__ src, float* __restrict__ dst)
{
    size_t i = ((size_t)blockIdx.x * blockDim.x + threadIdx.x);
    const size_t stride = (size_t)gridDim.x * blockDim.x;
    const size_t n4 = CB_N / 4;
    const float4* s4 = (const float4*)src;
    float4* d4 = (float4*)dst;
    for (; i < n4; i += stride) d4[i] = s4[i];
}

// ---------------------------------------------------------------------------
// Kernel 6: gather + center + L2-normalize + straight-through identity.
// ---------------------------------------------------------------------------
__global__ __launch_bounds__(256)
void quantize_kernel(const float* __restrict__ inputs,
                     const float* __restrict__ codebook,
                     float* __restrict__ qout)
{
    const int warp = threadIdx.x >> 5;
    const int lane = threadIdx.x & 31;
    const int tok = blockIdx.x * 8 + warp;
    const int idx = g_nn[tok];
    const float* row = codebook + (size_t)idx * D_DIM;

    float4 x[8];
    float sum = 0.f;
#pragma unroll
    for (int c = 0; c < 8; ++c) {
        x[c] = *(const float4*)(row + c * 128 + lane * 4);
        sum += x[c].x + x[c].y + x[c].z + x[c].w;
    }
#pragma unroll
    for (int off = 16; off > 0; off >>= 1)
        sum += __shfl_xor_sync(0xffffffffu, sum, off);
    const float mean = sum * (1.f / (float)D_DIM);

    float ss = 0.f;
#pragma unroll
    for (int c = 0; c < 8; ++c) {
        x[c].x -= mean; x[c].y -= mean; x[c].z -= mean; x[c].w -= mean;
        ss += x[c].x * x[c].x + x[c].y * x[c].y + x[c].z * x[c].z + x[c].w * x[c].w;
    }
#pragma unroll
    for (int off = 16; off > 0; off >>= 1)
        ss += __shfl_xor_sync(0xffffffffu, ss, off);
    const float invn = 1.f / sqrtf(ss);

    const float* xin = inputs + (size_t)tok * D_DIM;
    float* out = qout + (size_t)tok * D_DIM;
#pragma unroll
    for (int c = 0; c < 8; ++c) {
        float4 iv = *(const float4*)(xin + c * 128 + lane * 4);
        float4 v;
        v.x = iv.x + (x[c].x * invn - iv.x);
        v.y = iv.y + (x[c].y * invn - iv.y);
        v.z = iv.z + (x[c].z * invn - iv.z);
        v.w = iv.w + (x[c].w * invn - iv.w);
        *(float4*)(out + c * 128 + lane * 4) = v;
    }
}

// ---------------------------------------------------------------------------
extern "C" void kernel_launch(void* const* d_in, const int* in_sizes, int n_in,
                              void* d_out, int out_size)
{
    const float* inputs   = (const float*)d_in[0];
    const float* codebook = (const float*)d_in[1];
    float* out = (float*)d_out;

    float *logits;
    uint4 *Ahi, *Bhi;
    cudaGetSymbolAddress((void**)&logits, g_logits);
    cudaGetSymbolAddress((void**)&Ahi, g_Ahi);
    cudaGetSymbolAddress((void**)&Bhi, g_Bhi);

    // 0) convert fp32 -> bf16 hi, pre-tiled + swizzled
    split_kernel<<<(M_TOK * 128) / 256, 256>>>(inputs, Ahi, M_TOK * 128, 16, 1);
    split_kernel<<<(K_CODE * 128) / 256, 256>>>(codebook, Bhi, K_CODE * 128, 1, 16);

    // 1) single-split bf16 similarity GEMM, tile 128x128, 3-stage, 2 CTA/SM
    cudaFuncSetAttribute(gemm_bf16x1_mma_kernel,
                         cudaFuncAttributeMaxDynamicSharedMemorySize, G_SMEM_TOTAL);
    {
        dim3 grid(K_CODE / 128, M_TOK / 128);   // (16, 256), nt fastest
        gemm_bf16x1_mma_kernel<<<grid, 256, G_SMEM_TOTAL>>>(
            (const uint8_t*)Ahi, (const uint8_t*)Bhi, logits);
    }

    // 2) row pass (warp-per-token)
    row_pass_kernel<<<RP_WARPS / 8, 256>>>(logits);
    // 2b) fp64 refine of near-tied argmax -> final nn_idx
    refine_kernel<<<M_TOK / 8, 256>>>(inputs, codebook, out + NN_OFF);
    // 3) loss reduction
    div_reduce_kernel<<<16, 128>>>();
    finalize2_kernel<<<1, 256>>>();
    // 4) broadcast loss
    fill_loss_kernel<<<8192, 256>>>(out + LOSS_OFF);
    // 5) codebook passthrough
    copy_cb_kernel<<<2048, 256>>>(codebook, out + CB_OFF);
    // 6) quantized rows
    quantize_kernel<<<M_TOK / 8, 256>>>(inputs, codebook, out + QUANT_OFF);
}

// round 15
// speedup vs baseline: 3.4774x; 1.0285x over previous
#include <cuda_runtime.h>
#include <cuda_bf16.h>
#include <cstdint>
#include <cstddef>
#include <climits>

// ---------------------------------------------------------------------------
// Problem shape (fixed by the dataset)
//   inputs:   [16, 2048, 1024] f32  -> M = 32768 tokens, D = 1024
//   codebook: [2048, 1024]     f32  -> K = 2048 codes
// Outputs concatenated (f32):
//   quantized  [32768,1024]  @ 0
//   qloss      [32768,2048]  @ 33554432   (scalar broadcast)
//   nn_idx     [32768]       @ 100663296  (as float)
//   codebook   [2048,1024]   @ 100696064
// ---------------------------------------------------------------------------
#define M_TOK   32768
#define K_CODE  2048
#define D_DIM   1024

#define QUANT_OFF 0
#define LOSS_OFF  33554432
#define NN_OFF    100663296
#define CB_OFF    100696064
#define LOSS_N    67108864
#define CB_N      2097152

#define NCAND 16

// ------------------------- scratch (device globals) ------------------------
__device__ __nv_bfloat16 g_logits[(size_t)M_TOK * K_CODE];   // 128 MiB (bf16)

#define RP_WARPS 4096          // 512 CTAs x 8 warps, 8 tokens per warp
__device__ float g_div_part[(size_t)RP_WARPS * K_CODE];   // 32 MiB per-warp partials
__device__ float g_h_part[RP_WARPS];
__device__ float g_acc_part[16];
__device__ int   g_nn[M_TOK];
__device__ float g_loss[1];
__device__ int   g_cand_cnt[M_TOK];
__device__ int   g_cand_idx[M_TOK][NCAND];

// bf16 hi operands, pre-tiled + pre-SW128-swizzled into 16KB blocks of
// [128 rows x 64 cols bf16] (= 128 rows x 128B).
//   A blocks ordered [m_tile (256)][k_chunk (16)]
//   B blocks ordered [k_chunk (16)][n_block (16)]
__device__ uint4 g_Ahi[(size_t)M_TOK * D_DIM / 8];   // 64 MiB
__device__ uint4 g_Bhi[(size_t)K_CODE * D_DIM / 8];  // 4 MiB

// ------------------------- PTX helpers ---------------------------
__device__ __forceinline__ uint32_t smem_to_u32(const void* p) {
    uint32_t a;
    asm("{ .reg .u64 t; cvta.to.shared.u64 t, %1; cvt.u32.u64 %0, t; }" : "=r"(a) : "l"(p));
    return a;
}

__device__ __forceinline__ void cp_async16(uint32_t dst, const void* src) {
    asm volatile("cp.async.cg.shared.global [%0], [%1], 16;" :: "r"(dst), "l"(src) : "memory");
}
__device__ __forceinline__ void cp_commit() {
    asm volatile("cp.async.commit_group;" ::: "memory");
}
template <int N>
__device__ __forceinline__ void cp_wait() {
    asm volatile("cp.async.wait_group %0;" :: "n"(N) : "memory");
}

__device__ __forceinline__ void ldmatrix_x4(uint32_t& r0, uint32_t& r1,
                                            uint32_t& r2, uint32_t& r3, uint32_t addr) {
    asm volatile("ldmatrix.sync.aligned.m8n8.x4.shared.b16 {%0,%1,%2,%3}, [%4];"
                 : "=r"(r0), "=r"(r1), "=r"(r2), "=r"(r3) : "r"(addr));
}

__device__ __forceinline__ void mma_bf16(float* c, const uint32_t* a, const uint32_t* b) {
    asm volatile(
        "mma.sync.aligned.m16n8k16.row.col.f32.bf16.bf16.f32 "
        "{%0,%1,%2,%3}, {%4,%5,%6,%7}, {%8,%9}, {%0,%1,%2,%3};"
        : "+f"(c[0]), "+f"(c[1]), "+f"(c[2]), "+f"(c[3])
        : "r"(a[0]), "r"(a[1]), "r"(a[2]), "r"(a[3]), "r"(b[0]), "r"(b[1]));
}

// ---------------------------------------------------------------------------
// Kernel 0: fp32 -> bf16 (hi only), tiled into 16KB SW128-swizzled blocks.
// ---------------------------------------------------------------------------
__global__ __launch_bounds__(256)
void split_kernel(const float* __restrict__ src,
                  uint4* __restrict__ hi,
                  int nchunks, int tileStride, int kcStride)
{
    int i = blockIdx.x * blockDim.x + threadIdx.x;
    if (i >= nchunks) return;
    const int c8   = i & 127;
    const int row  = i >> 7;
    const int kc   = c8 >> 3;
    const int g    = c8 & 7;
    const int tile = row >> 7;
    const int r    = row & 127;

    const size_t blk = (size_t)tile * tileStride + (size_t)kc * kcStride;
    uint32_t off = r * 128 + g * 16;
    off ^= (off >> 3) & 0x70;                     // SW128 swizzle
    const size_t dst = blk * 1024 + (off >> 4);

    const float4* s4 = (const float4*)(src + ((size_t)row << 10) + (c8 << 3));
    float4 x0 = s4[0], x1 = s4[1];
    float xs[8] = {x0.x, x0.y, x0.z, x0.w, x1.x, x1.y, x1.z, x1.w};
    uint32_t hw[4];
#pragma unroll
    for (int j = 0; j < 4; ++j) {
        __nv_bfloat16 h0 = __float2bfloat16_rn(xs[2*j]);
        __nv_bfloat16 h1 = __float2bfloat16_rn(xs[2*j+1]);
        hw[j] = (uint32_t)__bfloat16_as_ushort(h0) | ((uint32_t)__bfloat16_as_ushort(h1) << 16);
    }
    hi[dst] = make_uint4(hw[0], hw[1], hw[2], hw[3]);
}

// ---------------------------------------------------------------------------
// Kernel 1: single-split bf16 GEMM via mma.sync:  C(bf16) ~= Ahi * Bhi^T.
// CTA tile 128(M) x 128(N), BK=64; 16 stages (one per k-chunk).
// 4 warps (128 thr), warp tile 64x64 (4 m-frags x 8 n-frags, 128 acc regs)
// -> LDSM:HMMA = 1:4, deep independent HMMA chains.
// 3-stage pipeline (96KB smem), 2 CTAs/SM.
// C stored as bf16 (halves epilogue traffic; quant err << GEMM err).
// ---------------------------------------------------------------------------
#define G_STAGE_BYTES 32768
#define G_SMEM_TOTAL  (3 * G_STAGE_BYTES)   // 98304

__device__ __forceinline__ void gemm_copy_stage(
    uint32_t sbuf, int kc, int mt, int nt, int tid,
    const uint8_t* Ahi, const uint8_t* Bhi)
{
    const uint8_t* ASrc = Ahi + ((size_t)(mt * 16 + kc)) * 16384;
    const uint8_t* BSrc = Bhi + ((size_t)(kc * 16 + nt)) * 16384;
#pragma unroll
    for (int i = 0; i < 8; ++i) {
        const int ch = tid + i * 128;
        cp_async16(sbuf + ch * 16,          ASrc + (size_t)ch * 16);
        cp_async16(sbuf + 16384 + ch * 16,  BSrc + (size_t)ch * 16);
    }
    cp_commit();
}

__global__ __launch_bounds__(128, 2)
void gemm_bf16x1_mma_kernel(const uint8_t* __restrict__ Ahi,
                            const uint8_t* __restrict__ Bhi,
                            __nv_bfloat16* __restrict__ C)
{
    extern __shared__ char smem[];
    const uint32_t sb = smem_to_u32(smem);
    const int tid = threadIdx.x;
    const int wid = tid >> 5;
    const int lane = tid & 31;
    const int nt = blockIdx.x;   // 0..15  (N tile of 128)  -- fastest: A reuse in L2
    const int mt = blockIdx.y;   // 0..255 (M tile of 128)

    const int wm = (wid >> 1) * 64;   // warp m offset (0 or 64)
    const int wn = (wid & 1) * 64;    // warp n offset (0 or 64)

    float acc[4][8][4];
#pragma unroll
    for (int i = 0; i < 4; ++i)
#pragma unroll
        for (int j = 0; j < 8; ++j)
#pragma unroll
            for (int r = 0; r < 4; ++r) acc[i][j][r] = 0.f;

    gemm_copy_stage(sb + 0 * G_STAGE_BYTES, 0, mt, nt, tid, Ahi, Bhi);
    gemm_copy_stage(sb + 1 * G_STAGE_BYTES, 1, mt, nt, tid, Ahi, Bhi);
    gemm_copy_stage(sb + 2 * G_STAGE_BYTES, 2, mt, nt, tid, Ahi, Bhi);

    const int lrow15 = lane & 15;
    const int lhalf  = lane >> 4;

    for (int it = 0; it < 16; ++it) {
        if (it < 14)       cp_wait<2>();
        else if (it == 14) cp_wait<1>();
        else               cp_wait<0>();
        __syncthreads();

        const uint32_t aBase = sb + (uint32_t)(it % 3) * G_STAGE_BYTES;
        const uint32_t bBase = aBase + 16384;

#pragma unroll
        for (int kk = 0; kk < 4; ++kk) {
            const int unit = 2 * kk + lhalf;
            uint32_t a[4][4];
            uint32_t b[8][2];
#pragma unroll
            for (int mi = 0; mi < 4; ++mi) {
                const int row = wm + mi * 16 + lrow15;
                ldmatrix_x4(a[mi][0], a[mi][1], a[mi][2], a[mi][3],
                            aBase + row * 128 + ((unit ^ (row & 7)) << 4));
            }
#pragma unroll
            for (int j = 0; j < 4; ++j) {
                const int row = wn + j * 16 + lrow15;
                uint32_t r0, r1, r2, r3;
                ldmatrix_x4(r0, r1, r2, r3,
                            bBase + row * 128 + ((unit ^ (row & 7)) << 4));
                b[2*j][0]   = r0; b[2*j][1]   = r2;
                b[2*j+1][0] = r1; b[2*j+1][1] = r3;
            }
#pragma unroll
            for (int mi = 0; mi < 4; ++mi)
#pragma unroll
                for (int ni = 0; ni < 8; ++ni)
                    mma_bf16(acc[mi][ni], a[mi], b[ni]);
        }

        __syncthreads();
        if (it + 3 < 16)
            gemm_copy_stage(sb + (uint32_t)((it + 3) % 3) * G_STAGE_BYTES,
                            it + 3, mt, nt, tid, Ahi, Bhi);
    }

    // epilogue: pack pairs of fp32 acc into bf16x2 words
    const int rbase = mt * 128 + wm + (lane >> 2);
    const int cbase = nt * 128 + wn + 2 * (lane & 3);
#pragma unroll
    for (int mi = 0; mi < 4; ++mi) {
#pragma unroll
        for (int ni = 0; ni < 8; ++ni) {
            const int r0 = rbase + mi * 16;
            const int c0 = cbase + ni * 8;
            uint32_t w0 = (uint32_t)__bfloat16_as_ushort(__float2bfloat16_rn(acc[mi][ni][0]))
                        | ((uint32_t)__bfloat16_as_ushort(__float2bfloat16_rn(acc[mi][ni][1])) << 16);
            uint32_t w1 = (uint32_t)__bfloat16_as_ushort(__float2bfloat16_rn(acc[mi][ni][2]))
                        | ((uint32_t)__bfloat16_as_ushort(__float2bfloat16_rn(acc[mi][ni][3])) << 16);
            *(uint32_t*)(C + (size_t)r0 * K_CODE + c0)       = w0;
            *(uint32_t*)(C + (size_t)(r0 + 8) * K_CODE + c0) = w1;
        }
    }
}

// ---------------------------------------------------------------------------
// fast 2^y (degree-4 poly after round-to-nearest split; rel err ~4e-5,
// far below the loss error budget). Avoids the MUFU throughput cliff.
// ---------------------------------------------------------------------------
__device__ __forceinline__ float fast_exp2(float y)
{
    float r = rintf(y);
    float f = y - r;
    float p = 9.6181291e-3f;
    p = fmaf(p, f, 5.5504109e-2f);
    p = fmaf(p, f, 2.4022651e-1f);
    p = fmaf(p, f, 6.9314718e-1f);
    p = fmaf(p, f, 1.0f);
    int ei = (int)r;
    if (ei < -126) return 0.f;
    float s = __int_as_float((ei + 127) << 23);
    return p * s;
}

// ---------------------------------------------------------------------------
// Kernel 2: row pass over bf16 logits, warp-per-token (no block syncs).
// 512 CTAs x 8 warps, 8 tokens/warp. Lane holds 64 logits (from 8 uint4 of
// bf16x8); warp-shuffle reductions; coalesced per-warp diversity partials.
// Candidate threshold 1.25 covers the single-split GEMM + bf16-store error.
// col(j) = 8*lane + 256*(j>>3) + (j&7)
// ---------------------------------------------------------------------------
__global__ __launch_bounds__(256)
void row_pass_kernel(const __nv_bfloat16* __restrict__ S)
{
    const int lane = threadIdx.x & 31;
    const int warp = threadIdx.x >> 5;
    const int gw = blockIdx.x * 8 + warp;        // global warp id, 0..4095

    float dreg[64];
#pragma unroll
    for (int j = 0; j < 64; ++j) dreg[j] = 0.f;
    float hsum = 0.f;

    for (int t = 0; t < 8; ++t) {
        const int tok = gw * 8 + t;
        const uint4* row4 = (const uint4*)(S + (size_t)tok * K_CODE);

        float v[64];
#pragma unroll
        for (int jj = 0; jj < 8; ++jj) {
            uint4 x = row4[lane + 32 * jj];
            const uint32_t w[4] = {x.x, x.y, x.z, x.w};
#pragma unroll
            for (int wi = 0; wi < 4; ++wi) {
                v[jj*8 + 2*wi + 0] = __uint_as_float(w[wi] << 16);
                v[jj*8 + 2*wi + 1] = __uint_as_float(w[wi] & 0xffff0000u);
            }
        }

        // ---- max (warp) ----
        float m = v[0];
#pragma unroll
        for (int j = 1; j < 64; ++j) m = fmaxf(m, v[j]);
#pragma unroll
        for (int off = 16; off > 0; off >>= 1)
            m = fmaxf(m, __shfl_xor_sync(0xffffffffu, m, off));

        // ---- candidates within 1.25 of max ----
        const float thr = m - 1.25f;
        int cnt_l = 0;
#pragma unroll
        for (int j = 0; j < 64; ++j) cnt_l += (v[j] >= thr) ? 1 : 0;
        int pre = cnt_l;
#pragma unroll
        for (int off = 1; off < 32; off <<= 1) {
            int n = __shfl_up_sync(0xffffffffu, pre, off);
            if (lane >= off) pre += n;
        }
        const int total = __shfl_sync(0xffffffffu, pre, 31);
        int slot = pre - cnt_l;   // exclusive prefix
        if (cnt_l) {
#pragma unroll
            for (int j = 0; j < 64; ++j) {
                if (v[j] >= thr) {
                    if (slot < NCAND)
                        g_cand_idx[tok][slot] = 8 * lane + 256 * (j >> 3) + (j & 7);
                    ++slot;
                }
            }
        }
        if (lane == 0) g_cand_cnt[tok] = (total < NCAND) ? total : NCAND;

        // ---- softmax stats ----
        const float LOG2E = 1.4426950408889634f;
        float s0 = 0.f, s1 = 0.f;
#pragma unroll
        for (int j = 0; j < 64; ++j) {
            float y = (v[j] - m) * LOG2E;
            float e = fast_exp2(y);
            v[j] = e;
            s0 += e;
            s1 = fmaf(e, y, s1);
        }
#pragma unroll
        for (int off = 16; off > 0; off >>= 1) {
            s0 += __shfl_xor_sync(0xffffffffu, s0, off);
            s1 += __shfl_xor_sync(0xffffffffu, s1, off);
        }
        const float inv = 1.f / s0;
#pragma unroll
        for (int j = 0; j < 64; ++j) dreg[j] = fmaf(v[j], inv, dreg[j]);
        hsum += s1 * inv - log2f(s0);
    }

    // per-warp diversity partial; dreg[jj*8+e] -> col 8*lane + 256*jj + e
    float4* dp = (float4*)(g_div_part + (size_t)gw * K_CODE);
#pragma unroll
    for (int jj = 0; jj < 8; ++jj) {
        dp[2*lane + 64*jj]     = make_float4(dreg[jj*8+0], dreg[jj*8+1], dreg[jj*8+2], dreg[jj*8+3]);
        dp[2*lane + 64*jj + 1] = make_float4(dreg[jj*8+4], dreg[jj*8+5], dreg[jj*8+6], dreg[jj*8+7]);
    }
    if (lane == 0) g_h_part[gw] = hsum;
}

// ---------------------------------------------------------------------------
// Kernel 2b: fp64 refinement of argmax among candidates (1 warp/token).
// ---------------------------------------------------------------------------
__global__ __launch_bounds__(256)
void refine_kernel(const float* __restrict__ inputs,
                   const float* __restrict__ codebook,
                   float* __restrict__ nn_out)
{
    const int warp = threadIdx.x >> 5;
    const int lane = threadIdx.x & 31;
    const int tok = blockIdx.x * 8 + warp;

    const int cnt = g_cand_cnt[tok];
    int best = g_cand_idx[tok][0];

    if (cnt > 1) {
        const float* xr = inputs + (size_t)tok * D_DIM;
        double bv = -1e300;
        int bi = INT_MAX;
        for (int c = 0; c < cnt; ++c) {
            const int idx = g_cand_idx[tok][c];
            const float* cr = codebook + (size_t)idx * D_DIM;
            double s = 0.0;
            for (int i = lane; i < D_DIM; i += 32)
                s += (double)xr[i] * (double)cr[i];
#pragma unroll
            for (int off = 16; off > 0; off >>= 1)
                s += __shfl_down_sync(0xffffffffu, s, off);
            s = __shfl_sync(0xffffffffu, s, 0);
            if (s > bv || (s == bv && idx < bi)) { bv = s; bi = idx; }
        }
        best = bi;
    }

    if (lane == 0) {
        g_nn[tok] = best;
        nn_out[tok] = (float)best;
    }
}

// ---------------------------------------------------------------------------
// Kernel 3a: diversity reduce across the 4096 per-warp partials (16 CTAs).
// ---------------------------------------------------------------------------
__global__ __launch_bounds__(128)
void div_reduce_kernel()
{
    const int col = blockIdx.x * 128 + threadIdx.x;
    float s = 0.f;
#pragma unroll 8
    for (int w = 0; w < RP_WARPS; ++w)
        s += g_div_part[(size_t)w * K_CODE + col];
    float dv = s * (1.f / (float)M_TOK);
    float acc = dv * log2f(dv + 1e-8f);

    __shared__ float sa[128];
    sa[threadIdx.x] = acc;
    __syncthreads();
    for (int off = 64; off > 0; off >>= 1) {
        if (threadIdx.x < off) sa[threadIdx.x] += sa[threadIdx.x + off];
        __syncthreads();
    }
    if (threadIdx.x == 0) g_acc_part[blockIdx.x] = sa[0];
}

// ---------------------------------------------------------------------------
// Kernel 3b: final scalar loss.
// ---------------------------------------------------------------------------
__global__ __launch_bounds__(256)
void finalize2_kernel()
{
    const int tid = threadIdx.x;
    float h = 0.f;
#pragma unroll
    for (int i = 0; i < RP_WARPS / 256; ++i)     // 16 per thread
        h += g_h_part[tid * (RP_WARPS / 256) + i];
    float a = (tid < 16) ? g_acc_part[tid] : 0.f;

    __shared__ float sh[256], sa[256];
    sh[tid] = h; sa[tid] = a;
    __syncthreads();
    for (int off = 128; off > 0; off >>= 1) {
        if (tid < off) { sh[tid] += sh[tid + off]; sa[tid] += sa[tid + off]; }
        __syncthreads();
    }
    if (tid == 0) {
        float h_clust = -sh[0] / (float)M_TOK;
        g_loss[0] = h_clust + sa[0];   // loss = h_clust - (-sa) = h_clust + sa
    }
}

// ---------------------------------------------------------------------------
// Kernel 4: broadcast scalar loss into the qloss region.
// ---------------------------------------------------------------------------
__global__ __launch_bounds__(256)
void fill_loss_kernel(float* __restrict__ dst)
{
    const float v = g_loss[0];
    const float4 v4 = make_float4(v, v, v, v);
    size_t i = ((size_t)blockIdx.x * blockDim.x + threadIdx.x);
    const size_t stride = (size_t)gridDim.x * blockDim.x;
    const size_t n4 = LOSS_N / 4;
    float4* d4 = (float4*)dst;
    for (; i < n4; i += stride) d4[i] = v4;
}

// ---------------------------------------------------------------------------
// Kernel 5: copy codebook into output.
// ---------------------------------------------------------------------------
__global__ __launch_bounds__(256)
void copy_cb_kernel(const float* __restrict__ src, float* __restrict__ dst)
{
    size_t i = ((size_t)blockIdx.x * blockDim.x + threadIdx.x);
    const size_t stride = (size_t)gridDim.x * blockDim.x;
    const size_t n4 = CB_N / 4;
    const float4* s4 = (const float4*)src;
    float4* d4 = (float4*)dst;
    for (; i < n4; i += stride) d4[i] = s4[i];
}

// ---------------------------------------------------------------------------
// Kernel 6: gather + center + L2-normalize + straight-through identity.
// ---------------------------------------------------------------------------
__global__ __launch_bounds__(256)
void quantize_kernel(const float* __restrict__ inputs,
                     const float* __restrict__ codebook,
                     float* __restrict__ qout)
{
    const int warp = threadIdx.x >> 5;
    const int lane = threadIdx.x & 31;
    const int tok = blockIdx.x * 8 + warp;
    const int idx = g_nn[tok];
    const float* row = codebook + (size_t)idx * D_DIM;

    float4 x[8];
    float sum = 0.f;
#pragma unroll
    for (int c = 0; c < 8; ++c) {
        x[c] = *(const float4*)(row + c * 128 + lane * 4);
        sum += x[c].x + x[c].y + x[c].z + x[c].w;
    }
#pragma unroll
    for (int off = 16; off > 0; off >>= 1)
        sum += __shfl_xor_sync(0xffffffffu, sum, off);
    const float mean = sum * (1.f / (float)D_DIM);

    float ss = 0.f;
#pragma unroll
    for (int c = 0; c < 8; ++c) {
        x[c].x -= mean; x[c].y -= mean; x[c].z -= mean; x[c].w -= mean;
        ss += x[c].x * x[c].x + x[c].y * x[c].y + x[c].z * x[c].z + x[c].w * x[c].w;
    }
#pragma unroll
    for (int off = 16; off > 0; off >>= 1)
        ss += __shfl_xor_sync(0xffffffffu, ss, off);
    const float invn = 1.f / sqrtf(ss);

    const float* xin = inputs + (size_t)tok * D_DIM;
    float* out = qout + (size_t)tok * D_DIM;
#pragma unroll
    for (int c = 0; c < 8; ++c) {
        float4 iv = *(const float4*)(xin + c * 128 + lane * 4);
        float4 v;
        v.x = iv.x + (x[c].x * invn - iv.x);
        v.y = iv.y + (x[c].y * invn - iv.y);
        v.z = iv.z + (x[c].z * invn - iv.z);
        v.w = iv.w + (x[c].w * invn - iv.w);
        *(float4*)(out + c * 128 + lane * 4) = v;
    }
}

// ---------------------------------------------------------------------------
extern "C" void kernel_launch(void* const* d_in, const int* in_sizes, int n_in,
                              void* d_out, int out_size)
{
    const float* inputs   = (const float*)d_in[0];
    const float* codebook = (const float*)d_in[1];
    float* out = (float*)d_out;

    __nv_bfloat16 *logits;
    uint4 *Ahi, *Bhi;
    cudaGetSymbolAddress((void**)&logits, g_logits);
    cudaGetSymbolAddress((void**)&Ahi, g_Ahi);
    cudaGetSymbolAddress((void**)&Bhi, g_Bhi);

    // 0) convert fp32 -> bf16 hi, pre-tiled + swizzled
    split_kernel<<<(M_TOK * 128) / 256, 256>>>(inputs, Ahi, M_TOK * 128, 16, 1);
    split_kernel<<<(K_CODE * 128) / 256, 256>>>(codebook, Bhi, K_CODE * 128, 1, 16);

    // 1) single-split bf16 similarity GEMM, 64x64 warp tiles, 2 CTA/SM
    cudaFuncSetAttribute(gemm_bf16x1_mma_kernel,
                         cudaFuncAttributeMaxDynamicSharedMemorySize, G_SMEM_TOTAL);
    {
        dim3 grid(K_CODE / 128, M_TOK / 128);   // (16, 256), nt fastest
        gemm_bf16x1_mma_kernel<<<grid, 128, G_SMEM_TOTAL>>>(
            (const uint8_t*)Ahi, (const uint8_t*)Bhi, logits);
    }

    // 2) row pass (warp-per-token, bf16 logits)
    row_pass_kernel<<<RP_WARPS / 8, 256>>>(logits);
    // 2b) fp64 refine of near-tied argmax -> final nn_idx
    refine_kernel<<<M_TOK / 8, 256>>>(inputs, codebook, out + NN_OFF);
    // 3) loss reduction
    div_reduce_kernel<<<16, 128>>>();
    finalize2_kernel<<<1, 256>>>();
    // 4) broadcast loss
    fill_loss_kernel<<<8192, 256>>>(out + LOSS_OFF);
    // 5) codebook passthrough
    copy_cb_kernel<<<2048, 256>>>(codebook, out + CB_OFF);
    // 6) quantized rows
    quantize_kernel<<<M_TOK / 8, 256>>>(inputs, codebook, out + QUANT_OFF);
}